// round 4
// baseline (speedup 1.0000x reference)
#include <cuda_runtime.h>
#include <cuda_bf16.h>
#include <cstdint>

// ---------------------------------------------------------------------------
// BiMamba refiner block, round 3: tf32x2 tensor-core GEMMs (mma.sync m16n8k8),
// error-compensated hi/lo split for fp32-class accuracy.
// B=2, T=4, N=196 -> L=784, M=1568. D_MODEL=768, D_INNER=1536, DS=16, DR=48.
// ---------------------------------------------------------------------------

#define BB      2
#define TT      4
#define NP      196
#define LL      784
#define MM      1568
#define CM      768
#define DI      1536
#define DS      16
#define DR      48
#define DCONV   4

// ---------------- scratch ---------------------------------------------------
__device__ float g_xn  [2 * MM * CM];
__device__ float g_xz  [2 * MM * 2 * DI];
__device__ float g_xb  [2 * MM * DI];
__device__ float g_xdbl[2 * MM * 80];
__device__ float g_dt  [2 * MM * DI];
__device__ float g_y   [2 * MM * DI];
__device__ float g_out [MM * 2 * CM];
__device__ float g_comb[MM * CM];
__device__ float g_A   [2 * DI * DS];
__device__ int   g_arith;

__device__ __forceinline__ int map_row(int l, int dir) {
    if (dir == 0) return l;
    int t = l / NP, n = l - t * NP;
    return (TT - 1 - t) * NP + n;
}
__device__ __forceinline__ float sigmoidf_(float v) { return 1.0f / (1.0f + __expf(-v)); }
__device__ __forceinline__ float siluf_(float v)    { return v * sigmoidf_(v); }

// tf32 split: x ~= hi + lo, both tf32-representable
__device__ __forceinline__ void split_tf32(float x, float& hi, float& lo) {
    uint32_t h;
    asm("cvt.rna.tf32.f32 %0, %1;" : "=r"(h) : "f"(x));
    float hf = __uint_as_float(h);
    float r  = x - hf;
    uint32_t l;
    asm("cvt.rna.tf32.f32 %0, %1;" : "=r"(l) : "f"(r));
    hi = hf; lo = __uint_as_float(l);
}

__device__ __forceinline__ void mma_tf32(float c[4],
                                         uint32_t a0, uint32_t a1, uint32_t a2, uint32_t a3,
                                         uint32_t b0, uint32_t b1) {
    asm volatile(
        "mma.sync.aligned.m16n8k8.row.col.f32.tf32.tf32.f32 "
        "{%0,%1,%2,%3},{%4,%5,%6,%7},{%8,%9},{%0,%1,%2,%3};"
        : "+f"(c[0]), "+f"(c[1]), "+f"(c[2]), "+f"(c[3])
        : "r"(a0), "r"(a1), "r"(a2), "r"(a3), "r"(b0), "r"(b1));
}

// ---------------------------------------------------------------------------
__global__ void setup_A_kernel(const float* __restrict__ A_log) {
    int i = blockIdx.x * blockDim.x + threadIdx.x;
    if (i < 2 * DI * DS) g_A[i] = -expf(A_log[i]);
}

__global__ void check_arith_kernel() {
    __shared__ int bad;
    if (threadIdx.x == 0) bad = 0;
    __syncthreads();
    for (int row = threadIdx.x; row < 2 * DI; row += blockDim.x) {
        const float* a = &g_A[row * DS];
        float a0 = a[0], da = a[1] - a[0];
        for (int n = 2; n < DS; n++) {
            float expect = a0 + n * da;
            if (fabsf(a[n] - expect) > 1e-4f * (1.0f + fabsf(a[n]))) { bad = 1; break; }
        }
    }
    __syncthreads();
    if (threadIdx.x == 0) g_arith = bad ? 0 : 1;
}

__global__ void rmsnorm_kernel(const float* __restrict__ x,
                               const float* __restrict__ norm_w) {
    int gid = blockIdx.x;
    int dir = gid / MM;
    int rem = gid - dir * MM;
    int b   = rem / LL, l = rem - b * LL;
    int lo  = map_row(l, dir);
    const float* row = x + (size_t)(b * LL + lo) * CM;

    float s = 0.f;
    for (int c = threadIdx.x; c < CM; c += blockDim.x) {
        float v = row[c];
        s += v * v;
    }
    __shared__ float warp_s[8];
    for (int off = 16; off > 0; off >>= 1) s += __shfl_down_sync(0xffffffffu, s, off);
    if ((threadIdx.x & 31) == 0) warp_s[threadIdx.x >> 5] = s;
    __syncthreads();
    if (threadIdx.x < 8) {
        float t = warp_s[threadIdx.x];
        for (int off = 4; off > 0; off >>= 1) t += __shfl_down_sync(0xffu, t, off);
        if (threadIdx.x == 0) warp_s[0] = t;
    }
    __syncthreads();
    float scale = rsqrtf(warp_s[0] / (float)CM + 1e-5f);

    float* dst = g_xn + (size_t)gid * CM;
    const float* nw = norm_w + dir * CM;
    for (int c = threadIdx.x; c < CM; c += blockDim.x)
        dst[c] = row[c] * scale * nw[c];
}

// ---------------------------------------------------------------------------
// tf32x2 tensor-core GEMM: C[M,N] = A[M,K] * W[N,K]^T
// BM=128, BN=128, BK=8. 256 threads = 8 warps (2 m x 4 n), warp tile 64x32.
// Per warp: 4 m-frags (m16) x 4 n-frags (n8), 3 MMAs each (hh, hl, lh).
// ---------------------------------------------------------------------------
#define EPI_STORE    0
#define EPI_SOFTPLUS 1
#define EPI_RESID    2
#define EPI_GATE     3
#define EPI_BIAS     4

template <int EPI>
__global__ void __launch_bounds__(256)
gemm_mma(const float* __restrict__ Ab, int lda, size_t sA,
         const float* __restrict__ Wb, size_t sW,
         float* __restrict__ Cb, int ldc, size_t sC,
         int M, int N, int K,
         const float* __restrict__ biasb, size_t sBias,
         const float* __restrict__ aux) {
    constexpr int BM = 128, BN = 128, BK = 8;

    __shared__ float Ah[2][BK][BM + 4], Al[2][BK][BM + 4];
    __shared__ float Bh[2][BK][BN + 4], Bl[2][BK][BN + 4];

    const int t    = threadIdx.x;
    const int lane = t & 31;
    const int w    = t >> 5;          // 0..7
    const int wm   = (w & 1) * 64;    // warp m offset in tile
    const int wn   = (w >> 1) * 32;   // warp n offset in tile
    const int g    = lane >> 2;       // 0..7
    const int tg   = lane & 3;        // 0..3

    const int m0  = blockIdx.y * BM;
    const int n0  = blockIdx.x * BN;
    const int dir = blockIdx.z;

    const float* A = Ab + (size_t)dir * sA;
    const float* W = Wb + (size_t)dir * sW;
    float*       C = Cb + (size_t)dir * sC;
    const float* bias = biasb ? biasb + (size_t)dir * sBias : nullptr;

    // gmem->reg staging: 1 float4 per thread per tile (BM*BK = 1024 floats)
    float4 ra, rb;
    const int lm = t >> 1;           // 0..127 row in tile
    const int lk = (t & 1) * 4;      // 0 or 4

    auto gload = [&](int k0) {
        float4 v = make_float4(0.f, 0.f, 0.f, 0.f);
        int gm = m0 + lm;
        if (gm < M) v = *(const float4*)&A[(size_t)gm * lda + k0 + lk];
        ra = v;
        v = make_float4(0.f, 0.f, 0.f, 0.f);
        int gn = n0 + lm;
        if (gn < N) v = *(const float4*)&W[(size_t)gn * K + k0 + lk];
        rb = v;
    };
    auto sstore = [&](int s) {
        float hi, lo;
        split_tf32(ra.x, hi, lo); Ah[s][lk + 0][lm] = hi; Al[s][lk + 0][lm] = lo;
        split_tf32(ra.y, hi, lo); Ah[s][lk + 1][lm] = hi; Al[s][lk + 1][lm] = lo;
        split_tf32(ra.z, hi, lo); Ah[s][lk + 2][lm] = hi; Al[s][lk + 2][lm] = lo;
        split_tf32(ra.w, hi, lo); Ah[s][lk + 3][lm] = hi; Al[s][lk + 3][lm] = lo;
        split_tf32(rb.x, hi, lo); Bh[s][lk + 0][lm] = hi; Bl[s][lk + 0][lm] = lo;
        split_tf32(rb.y, hi, lo); Bh[s][lk + 1][lm] = hi; Bl[s][lk + 1][lm] = lo;
        split_tf32(rb.z, hi, lo); Bh[s][lk + 2][lm] = hi; Bl[s][lk + 2][lm] = lo;
        split_tf32(rb.w, hi, lo); Bh[s][lk + 3][lm] = hi; Bl[s][lk + 3][lm] = lo;
    };

    float acc[4][4][4];
#pragma unroll
    for (int i = 0; i < 4; i++)
#pragma unroll
        for (int j = 0; j < 4; j++)
#pragma unroll
            for (int r = 0; r < 4; r++) acc[i][j][r] = 0.f;

    const int nk = K / BK;
    gload(0);
    sstore(0);
    __syncthreads();

    int cur = 0;
    for (int kt = 0; kt < nk; kt++) {
        if (kt + 1 < nk) gload((kt + 1) * BK);

        // fragment loads (m16n8k8: a0=(g,tg) a1=(g+8,tg) a2=(g,tg+4) a3=(g+8,tg+4);
        //                 b0=(k=tg,n=g) b1=(k=tg+4,n=g))
        uint32_t ah[4][4], al[4][4], bh[4][2], bl[4][2];
#pragma unroll
        for (int i = 0; i < 4; i++) {
            int mb = wm + i * 16;
            ah[i][0] = __float_as_uint(Ah[cur][tg    ][mb + g    ]);
            ah[i][1] = __float_as_uint(Ah[cur][tg    ][mb + g + 8]);
            ah[i][2] = __float_as_uint(Ah[cur][tg + 4][mb + g    ]);
            ah[i][3] = __float_as_uint(Ah[cur][tg + 4][mb + g + 8]);
            al[i][0] = __float_as_uint(Al[cur][tg    ][mb + g    ]);
            al[i][1] = __float_as_uint(Al[cur][tg    ][mb + g + 8]);
            al[i][2] = __float_as_uint(Al[cur][tg + 4][mb + g    ]);
            al[i][3] = __float_as_uint(Al[cur][tg + 4][mb + g + 8]);
        }
#pragma unroll
        for (int j = 0; j < 4; j++) {
            int nb = wn + j * 8;
            bh[j][0] = __float_as_uint(Bh[cur][tg    ][nb + g]);
            bh[j][1] = __float_as_uint(Bh[cur][tg + 4][nb + g]);
            bl[j][0] = __float_as_uint(Bl[cur][tg    ][nb + g]);
            bl[j][1] = __float_as_uint(Bl[cur][tg + 4][nb + g]);
        }

#pragma unroll
        for (int i = 0; i < 4; i++)
#pragma unroll
            for (int j = 0; j < 4; j++) {
                mma_tf32(acc[i][j], ah[i][0], ah[i][1], ah[i][2], ah[i][3], bh[j][0], bh[j][1]);
                mma_tf32(acc[i][j], ah[i][0], ah[i][1], ah[i][2], ah[i][3], bl[j][0], bl[j][1]);
                mma_tf32(acc[i][j], al[i][0], al[i][1], al[i][2], al[i][3], bh[j][0], bh[j][1]);
            }

        __syncthreads();
        if (kt + 1 < nk) {
            sstore(cur ^ 1);
            __syncthreads();
            cur ^= 1;
        }
    }

    // epilogue: c0=(g, 2tg) c1=(g, 2tg+1) c2=(g+8, 2tg) c3=(g+8, 2tg+1)
    auto emit = [&](int m, int n, float v) {
        if (m >= M || n >= N) return;
        if (EPI == EPI_STORE) {
            C[(size_t)m * ldc + n] = v;
        } else if (EPI == EPI_SOFTPLUS) {
            v += bias[n];
            C[(size_t)m * ldc + n] = (v > 20.f) ? v : log1pf(__expf(v));
        } else if (EPI == EPI_RESID) {
            int b = m / LL, l = m - b * LL;
            int lo = map_row(l, dir);
            int row = b * LL + lo;
            C[((size_t)row * 2 + dir) * CM + n] = aux[(size_t)row * CM + n] + v;
        } else if (EPI == EPI_GATE) {
            float gg = sigmoidf_(v + bias[n]);
            float of = aux[(size_t)m * (2 * CM) + n];
            float ob = aux[(size_t)m * (2 * CM) + CM + n];
            C[(size_t)m * ldc + n] = gg * of + (1.f - gg) * ob;
        } else {
            C[(size_t)m * ldc + n] = v + bias[n];
        }
    };

#pragma unroll
    for (int i = 0; i < 4; i++) {
        int mr = m0 + wm + i * 16 + g;
#pragma unroll
        for (int j = 0; j < 4; j++) {
            int nc = n0 + wn + j * 8 + 2 * tg;
            emit(mr,     nc,     acc[i][j][0]);
            emit(mr,     nc + 1, acc[i][j][1]);
            emit(mr + 8, nc,     acc[i][j][2]);
            emit(mr + 8, nc + 1, acc[i][j][3]);
        }
    }
}

// ---------------------------------------------------------------------------
// SIMT split-K GEMM for the skinny x_proj (N=80). Same as round 2.
// ---------------------------------------------------------------------------
template <int TM, int TN, int TK, int KS>
__global__ void __launch_bounds__(256, 2)
gemm_splitk(const float* __restrict__ Ab, int lda, size_t sA,
            const float* __restrict__ Wb, size_t sW,
            float* __restrict__ Cb, int ldc, size_t sC,
            int M, int N, int K) {
    constexpr int RM = TM / 16;
    constexpr int RN = TN / 16;
    constexpr int A4 = TM * TK / 4;
    constexpr int B4 = TN * TK / 4;
    constexpr int RA = (A4 + 255) / 256;
    constexpr int RB = (B4 + 255) / 256;

    __shared__ float As[2][TK][TM + 4];
    __shared__ float Bs[2][TK][TN + 4];

    const int t  = threadIdx.x;
    const int tx = t & 15;
    const int ty = t >> 4;
    const int m0 = blockIdx.y * TM;
    const int n0 = blockIdx.x * TN;

    const int z = blockIdx.z;
    const int dir   = z / KS;
    const int split = z % KS;

    const float* A = Ab + (size_t)dir * sA;
    const float* W = Wb + (size_t)dir * sW;
    float*       C = Cb + (size_t)dir * sC;

    const int Kpart = K / KS;
    const int kbeg  = split * Kpart;
    const int nk    = Kpart / TK;

    float4 ra[RA], rb[RB];

    auto gload = [&](int k0) {
#pragma unroll
        for (int i = 0; i < RA; i++) {
            int idx = t + i * 256;
            float4 v = make_float4(0.f, 0.f, 0.f, 0.f);
            if (idx < A4) {
                int m = idx / (TK / 4), kq = idx % (TK / 4);
                int gm = m0 + m;
                if (gm < M) v = *(const float4*)&A[(size_t)gm * lda + k0 + kq * 4];
            }
            ra[i] = v;
        }
#pragma unroll
        for (int i = 0; i < RB; i++) {
            int idx = t + i * 256;
            float4 v = make_float4(0.f, 0.f, 0.f, 0.f);
            if (idx < B4) {
                int n = idx / (TK / 4), kq = idx % (TK / 4);
                int gn = n0 + n;
                if (gn < N) v = *(const float4*)&W[(size_t)gn * K + k0 + kq * 4];
            }
            rb[i] = v;
        }
    };
    auto sstore = [&](int s) {
#pragma unroll
        for (int i = 0; i < RA; i++) {
            int idx = t + i * 256;
            if (idx < A4) {
                int m = idx / (TK / 4), kq = (idx % (TK / 4)) * 4;
                As[s][kq + 0][m] = ra[i].x; As[s][kq + 1][m] = ra[i].y;
                As[s][kq + 2][m] = ra[i].z; As[s][kq + 3][m] = ra[i].w;
            }
        }
#pragma unroll
        for (int i = 0; i < RB; i++) {
            int idx = t + i * 256;
            if (idx < B4) {
                int n = idx / (TK / 4), kq = (idx % (TK / 4)) * 4;
                Bs[s][kq + 0][n] = rb[i].x; Bs[s][kq + 1][n] = rb[i].y;
                Bs[s][kq + 2][n] = rb[i].z; Bs[s][kq + 3][n] = rb[i].w;
            }
        }
    };

    float acc[RM][RN];
#pragma unroll
    for (int i = 0; i < RM; i++)
#pragma unroll
        for (int j = 0; j < RN; j++) acc[i][j] = 0.f;

    gload(kbeg);
    sstore(0);
    __syncthreads();

    int cur = 0;
    for (int kt = 0; kt < nk; kt++) {
        if (kt + 1 < nk) gload(kbeg + (kt + 1) * TK);
#pragma unroll
        for (int k = 0; k < TK; k++) {
            float af[RM], bf[RN];
#pragma unroll
            for (int i = 0; i < RM; i++) af[i] = As[cur][k][ty * RM + i];
#pragma unroll
            for (int j = 0; j < RN; j++) bf[j] = Bs[cur][k][tx * RN + j];
#pragma unroll
            for (int i = 0; i < RM; i++)
#pragma unroll
                for (int j = 0; j < RN; j++)
                    acc[i][j] = fmaf(af[i], bf[j], acc[i][j]);
        }
        __syncthreads();
        if (kt + 1 < nk) {
            sstore(cur ^ 1);
            __syncthreads();
            cur ^= 1;
        }
    }

#pragma unroll
    for (int i = 0; i < RM; i++) {
        int m = m0 + ty * RM + i;
        if (m >= M) continue;
#pragma unroll
        for (int j = 0; j < RN; j++) {
            int n = n0 + tx * RN + j;
            if (n >= N) continue;
            atomicAdd(&C[(size_t)m * ldc + n], acc[i][j]);
        }
    }
}

// ---------------------------------------------------------------------------
__global__ void conv_silu_kernel(const float* __restrict__ conv_w,
                                 const float* __restrict__ conv_b) {
    int idx = blockIdx.x * blockDim.x + threadIdx.x;
    if (idx >= 2 * MM * DI) return;
    int d = idx % DI;
    int r = idx / DI;
    int dir = r / MM;
    int l = r % LL;

    const float* w = conv_w + (size_t)(dir * DI + d) * DCONV;
    float acc = conv_b[dir * DI + d];
#pragma unroll
    for (int j = 0; j < DCONV; j++) {
        int ls = l - (DCONV - 1) + j;
        if (ls >= 0)
            acc = fmaf(w[j], g_xz[(size_t)(r - (DCONV - 1) + j) * (2 * DI) + d], acc);
    }
    g_xb[(size_t)r * DI + d] = siluf_(acc);
}

// ---------------------------------------------------------------------------
__global__ void __launch_bounds__(128, 8)
scan_kernel(const float* __restrict__ Dp) {
    int d   = blockIdx.x * blockDim.x + threadIdx.x;
    int b   = blockIdx.y;
    int dir = blockIdx.z;
    if (d >= DI) return;

    const float* Arow = &g_A[(dir * DI + d) * DS];
    float a0 = Arow[0];
    float da = Arow[1] - Arow[0];
    float Ar[DS];
    bool arith = (g_arith != 0);
    if (!arith) {
#pragma unroll
        for (int n = 0; n < DS; n++) Ar[n] = Arow[n];
    }

    float h[DS];
#pragma unroll
    for (int n = 0; n < DS; n++) h[n] = 0.f;

    float Dd = Dp[dir * DI + d];
    size_t r0 = (size_t)dir * MM + (size_t)b * LL;

    for (int l = 0; l < LL; l++) {
        size_t r = r0 + l;
        float u  = g_xb[r * DI + d];
        float dt = g_dt[r * DI + d];
        const float4* BC = (const float4*)(&g_xdbl[r * 80 + DR]);
        float4 Bv0 = __ldg(&BC[0]), Bv1 = __ldg(&BC[1]);
        float4 Bv2 = __ldg(&BC[2]), Bv3 = __ldg(&BC[3]);
        float4 Cv0 = __ldg(&BC[4]), Cv1 = __ldg(&BC[5]);
        float4 Cv2 = __ldg(&BC[6]), Cv3 = __ldg(&BC[7]);
        float Bl[DS] = {Bv0.x, Bv0.y, Bv0.z, Bv0.w, Bv1.x, Bv1.y, Bv1.z, Bv1.w,
                        Bv2.x, Bv2.y, Bv2.z, Bv2.w, Bv3.x, Bv3.y, Bv3.z, Bv3.w};
        float Cl[DS] = {Cv0.x, Cv0.y, Cv0.z, Cv0.w, Cv1.x, Cv1.y, Cv1.z, Cv1.w,
                        Cv2.x, Cv2.y, Cv2.z, Cv2.w, Cv3.x, Cv3.y, Cv3.z, Cv3.w};

        float du = dt * u;
        float yv = 0.f;
        if (arith) {
            float p  = __expf(dt * a0);
            float rr = __expf(dt * da);
#pragma unroll
            for (int n = 0; n < DS; n++) {
                h[n] = fmaf(p, h[n], du * Bl[n]);
                yv   = fmaf(h[n], Cl[n], yv);
                p *= rr;
            }
        } else {
#pragma unroll
            for (int n = 0; n < DS; n++) {
                float p = __expf(dt * Ar[n]);
                h[n] = fmaf(p, h[n], du * Bl[n]);
                yv   = fmaf(h[n], Cl[n], yv);
            }
        }
        yv = fmaf(u, Dd, yv);
        float z = g_xz[r * (2 * DI) + DI + d];
        g_y[r * DI + d] = yv * siluf_(z);
    }
}

// ---------------------------------------------------------------------------
extern "C" void kernel_launch(void* const* d_in, const int* in_sizes, int n_in,
                              void* d_out, int out_size) {
    const float* x         = (const float*)d_in[0];
    const float* norm_w    = (const float*)d_in[1];
    const float* in_proj_w = (const float*)d_in[2];
    const float* conv_w    = (const float*)d_in[3];
    const float* conv_b    = (const float*)d_in[4];
    const float* x_proj_w  = (const float*)d_in[5];
    const float* dt_proj_w = (const float*)d_in[6];
    const float* dt_proj_b = (const float*)d_in[7];
    const float* A_log     = (const float*)d_in[8];
    const float* Dp        = (const float*)d_in[9];
    const float* mix_out_w = (const float*)d_in[10];
    const float* gate_w    = (const float*)d_in[11];
    const float* gate_b    = (const float*)d_in[12];
    const float* proj_w    = (const float*)d_in[13];
    const float* proj_b    = (const float*)d_in[14];
    float* out = (float*)d_out;

    float *xn, *xz, *xb, *xdbl, *dt, *y, *o_out, *comb;
    cudaGetSymbolAddress((void**)&xn,    g_xn);
    cudaGetSymbolAddress((void**)&xz,    g_xz);
    cudaGetSymbolAddress((void**)&xb,    g_xb);
    cudaGetSymbolAddress((void**)&xdbl,  g_xdbl);
    cudaGetSymbolAddress((void**)&dt,    g_dt);
    cudaGetSymbolAddress((void**)&y,     g_y);
    cudaGetSymbolAddress((void**)&o_out, g_out);
    cudaGetSymbolAddress((void**)&comb,  g_comb);

    setup_A_kernel<<<(2 * DI * DS + 255) / 256, 256>>>(A_log);
    check_arith_kernel<<<1, 256>>>();

    rmsnorm_kernel<<<2 * MM, 256>>>(x, norm_w);

    // in_proj: (1568x768) @ (3072x768)^T
    gemm_mma<EPI_STORE><<<dim3(2 * DI / 128, (MM + 127) / 128, 2), 256>>>(
        xn, CM, (size_t)MM * CM,
        in_proj_w, (size_t)2 * DI * CM,
        xz, 2 * DI, (size_t)MM * 2 * DI,
        MM, 2 * DI, CM, nullptr, 0, nullptr);

    conv_silu_kernel<<<(2 * MM * DI + 255) / 256, 256>>>(conv_w, conv_b);

    // x_proj: (1568x1536) @ (80x1536)^T, split-K=8 SIMT
    cudaMemsetAsync(xdbl, 0, sizeof(float) * 2 * MM * 80);
    gemm_splitk<128, 80, 16, 8><<<dim3(1, (MM + 127) / 128, 2 * 8), 256>>>(
        xb, DI, (size_t)MM * DI,
        x_proj_w, (size_t)80 * DI,
        xdbl, 80, (size_t)MM * 80,
        MM, 80, DI);

    // dt_proj + softplus: (1568x48) @ (1536x48)^T
    gemm_mma<EPI_SOFTPLUS><<<dim3(DI / 128, (MM + 127) / 128, 2), 256>>>(
        xdbl, 80, (size_t)MM * 80,
        dt_proj_w, (size_t)DI * DR,
        dt, DI, (size_t)MM * DI,
        MM, DI, DR, dt_proj_b, DI, nullptr);

    scan_kernel<<<dim3(DI / 128, BB, 2), 128>>>(Dp);

    // out_proj + residual + flip-scatter
    gemm_mma<EPI_RESID><<<dim3(CM / 128, (MM + 127) / 128, 2), 256>>>(
        y, DI, (size_t)MM * DI,
        mix_out_w, (size_t)CM * DI,
        o_out, 0, 0,
        MM, CM, DI, nullptr, 0, x);

    // gate GEMM + sigmoid combine
    gemm_mma<EPI_GATE><<<dim3(CM / 128, (MM + 127) / 128, 1), 256>>>(
        o_out, 2 * CM, 0,
        gate_w, 0,
        comb, CM, 0,
        MM, CM, 2 * CM, gate_b, 0, o_out);

    // final projection + bias
    gemm_mma<EPI_BIAS><<<dim3(CM / 128, (MM + 127) / 128, 1), 256>>>(
        comb, CM, 0,
        proj_w, 0,
        out, CM, 0,
        MM, CM, CM, proj_b, 0, nullptr);

    (void)in_sizes; (void)n_in; (void)out_size;
}

// round 5
// speedup vs baseline: 1.3459x; 1.3459x over previous
#include <cuda_runtime.h>
#include <cuda_bf16.h>
#include <cstdint>

// ---------------------------------------------------------------------------
// BiMamba refiner block, round 4: bf16x2 error-split tensor-core GEMMs
// (mma.sync.m16n8k16.bf16, 3 compensated MMAs per product), single-sync
// double-buffered pipeline, BN=64 for 2 CTAs/SM occupancy.
// ---------------------------------------------------------------------------

#define BB      2
#define TT      4
#define NP      196
#define LL      784
#define MM      1568
#define CM      768
#define DI      1536
#define DS      16
#define DR      48
#define DCONV   4

// ---------------- scratch ---------------------------------------------------
__device__ float g_xn  [2 * MM * CM];
__device__ float g_xz  [2 * MM * 2 * DI];
__device__ float g_xb  [2 * MM * DI];
__device__ float g_xdbl[2 * MM * 80];
__device__ float g_dt  [2 * MM * DI];
__device__ float g_y   [2 * MM * DI];
__device__ float g_out [MM * 2 * CM];
__device__ float g_comb[MM * CM];
__device__ float g_A   [2 * DI * DS];
__device__ int   g_arith;

__device__ __forceinline__ int map_row(int l, int dir) {
    if (dir == 0) return l;
    int t = l / NP, n = l - t * NP;
    return (TT - 1 - t) * NP + n;
}
__device__ __forceinline__ float sigmoidf_(float v) { return 1.0f / (1.0f + __expf(-v)); }
__device__ __forceinline__ float siluf_(float v)    { return v * sigmoidf_(v); }

// split two floats into packed bf16x2 hi and lo (k-even low half, k-odd high)
__device__ __forceinline__ void split2(float x, float y, uint32_t& hi, uint32_t& lo) {
    __nv_bfloat16 hx = __float2bfloat16(x);
    __nv_bfloat16 hy = __float2bfloat16(y);
    __nv_bfloat16 lx = __float2bfloat16(x - __bfloat162float(hx));
    __nv_bfloat16 ly = __float2bfloat16(y - __bfloat162float(hy));
    __nv_bfloat162 h2 = __halves2bfloat162(hx, hy);
    __nv_bfloat162 l2 = __halves2bfloat162(lx, ly);
    hi = *reinterpret_cast<uint32_t*>(&h2);
    lo = *reinterpret_cast<uint32_t*>(&l2);
}

__device__ __forceinline__ void mma_bf16(float c[4],
                                         uint32_t a0, uint32_t a1, uint32_t a2, uint32_t a3,
                                         uint32_t b0, uint32_t b1) {
    asm volatile(
        "mma.sync.aligned.m16n8k16.row.col.f32.bf16.bf16.f32 "
        "{%0,%1,%2,%3},{%4,%5,%6,%7},{%8,%9},{%0,%1,%2,%3};"
        : "+f"(c[0]), "+f"(c[1]), "+f"(c[2]), "+f"(c[3])
        : "r"(a0), "r"(a1), "r"(a2), "r"(a3), "r"(b0), "r"(b1));
}

// ---------------------------------------------------------------------------
__global__ void setup_A_kernel(const float* __restrict__ A_log) {
    int i = blockIdx.x * blockDim.x + threadIdx.x;
    if (i < 2 * DI * DS) g_A[i] = -expf(A_log[i]);
}

__global__ void check_arith_kernel() {
    __shared__ int bad;
    if (threadIdx.x == 0) bad = 0;
    __syncthreads();
    for (int row = threadIdx.x; row < 2 * DI; row += blockDim.x) {
        const float* a = &g_A[row * DS];
        float a0 = a[0], da = a[1] - a[0];
        for (int n = 2; n < DS; n++) {
            float expect = a0 + n * da;
            if (fabsf(a[n] - expect) > 1e-4f * (1.0f + fabsf(a[n]))) { bad = 1; break; }
        }
    }
    __syncthreads();
    if (threadIdx.x == 0) g_arith = bad ? 0 : 1;
}

__global__ void rmsnorm_kernel(const float* __restrict__ x,
                               const float* __restrict__ norm_w) {
    int gid = blockIdx.x;
    int dir = gid / MM;
    int rem = gid - dir * MM;
    int b   = rem / LL, l = rem - b * LL;
    int lo  = map_row(l, dir);
    const float* row = x + (size_t)(b * LL + lo) * CM;

    float s = 0.f;
    for (int c = threadIdx.x; c < CM; c += blockDim.x) {
        float v = row[c];
        s += v * v;
    }
    __shared__ float warp_s[8];
    for (int off = 16; off > 0; off >>= 1) s += __shfl_down_sync(0xffffffffu, s, off);
    if ((threadIdx.x & 31) == 0) warp_s[threadIdx.x >> 5] = s;
    __syncthreads();
    if (threadIdx.x < 8) {
        float t = warp_s[threadIdx.x];
        for (int off = 4; off > 0; off >>= 1) t += __shfl_down_sync(0xffu, t, off);
        if (threadIdx.x == 0) warp_s[0] = t;
    }
    __syncthreads();
    float scale = rsqrtf(warp_s[0] / (float)CM + 1e-5f);

    float* dst = g_xn + (size_t)gid * CM;
    const float* nw = norm_w + dir * CM;
    for (int c = threadIdx.x; c < CM; c += blockDim.x)
        dst[c] = row[c] * scale * nw[c];
}

// ---------------------------------------------------------------------------
// bf16x2 tensor-core GEMM: C[M,N] = A[M,K] * W[N,K]^T
// BM=128, BN=64, BK=16. 8 warps (2m x 4n), warp tile 64x16.
// smem: packed bf16x2 along k, rows = k-pair (8), cols = m/n.
// One __syncthreads per k-tile (store-next-after-compute).
// ---------------------------------------------------------------------------
#define EPI_STORE    0
#define EPI_SOFTPLUS 1
#define EPI_RESID    2
#define EPI_GATE     3
#define EPI_BIAS     4

template <int EPI>
__global__ void __launch_bounds__(256, 2)
gemm_bf16x2(const float* __restrict__ Ab, int lda, size_t sA,
            const float* __restrict__ Wb, size_t sW,
            float* __restrict__ Cb, int ldc, size_t sC,
            int M, int N, int K,
            const float* __restrict__ biasb, size_t sBias,
            const float* __restrict__ aux) {
    constexpr int BM = 128, BN = 64;
    constexpr int NF = 2;                 // n-frags per warp (warp n = 16)

    __shared__ uint32_t Ah[2][8][BM + 4], Al[2][8][BM + 4];
    __shared__ uint32_t Bh[2][8][BN + 4], Bl[2][8][BN + 4];

    const int t    = threadIdx.x;
    const int lane = t & 31;
    const int w    = t >> 5;
    const int wm   = (w & 1) * 64;
    const int wn   = (w >> 1) * 16;
    const int g    = lane >> 2;
    const int tg   = lane & 3;

    const int m0  = blockIdx.y * BM;
    const int n0  = blockIdx.x * BN;
    const int dir = blockIdx.z;

    const float* A = Ab + (size_t)dir * sA;
    const float* W = Wb + (size_t)dir * sW;
    float*       C = Cb + (size_t)dir * sC;
    const float* bias = biasb ? biasb + (size_t)dir * sBias : nullptr;

    // staging: A 128x16 = 2048 floats -> 8 per thread (row t>>1, k-half (t&1)*8)
    //          B  64x16 = 1024 floats -> 4 per thread (row t>>2, k-quarter (t&3)*4)
    const int alm = t >> 1;
    const int aka = (t & 1) * 8;
    const int bln = t >> 2;
    const int bkb = (t & 3) * 4;

    float4 ra0, ra1, rbv;
    auto gload = [&](int k0) {
        int gm = m0 + alm;
        if (gm < M) {
            ra0 = *(const float4*)&A[(size_t)gm * lda + k0 + aka];
            ra1 = *(const float4*)&A[(size_t)gm * lda + k0 + aka + 4];
        } else {
            ra0 = make_float4(0.f, 0.f, 0.f, 0.f);
            ra1 = ra0;
        }
        int gn = n0 + bln;
        if (gn < N) rbv = *(const float4*)&W[(size_t)gn * K + k0 + bkb];
        else        rbv = make_float4(0.f, 0.f, 0.f, 0.f);
    };
    auto sstore = [&](int s) {
        uint32_t hi, lo;
        int kp = aka >> 1;
        split2(ra0.x, ra0.y, hi, lo); Ah[s][kp + 0][alm] = hi; Al[s][kp + 0][alm] = lo;
        split2(ra0.z, ra0.w, hi, lo); Ah[s][kp + 1][alm] = hi; Al[s][kp + 1][alm] = lo;
        split2(ra1.x, ra1.y, hi, lo); Ah[s][kp + 2][alm] = hi; Al[s][kp + 2][alm] = lo;
        split2(ra1.z, ra1.w, hi, lo); Ah[s][kp + 3][alm] = hi; Al[s][kp + 3][alm] = lo;
        int kq = bkb >> 1;
        split2(rbv.x, rbv.y, hi, lo); Bh[s][kq + 0][bln] = hi; Bl[s][kq + 0][bln] = lo;
        split2(rbv.z, rbv.w, hi, lo); Bh[s][kq + 1][bln] = hi; Bl[s][kq + 1][bln] = lo;
    };

    float acc[4][NF][4];
#pragma unroll
    for (int i = 0; i < 4; i++)
#pragma unroll
        for (int j = 0; j < NF; j++)
#pragma unroll
            for (int r = 0; r < 4; r++) acc[i][j][r] = 0.f;

    const int nk = K / 16;
    gload(0);
    sstore(0);
    __syncthreads();

    int cur = 0;
    for (int kt = 0; kt < nk; kt++) {
        if (kt + 1 < nk) gload((kt + 1) * 16);

        uint32_t ah[4][4], al[4][4];
#pragma unroll
        for (int i = 0; i < 4; i++) {
            int mb = wm + i * 16;
            ah[i][0] = Ah[cur][tg    ][mb + g    ];
            ah[i][1] = Ah[cur][tg    ][mb + g + 8];
            ah[i][2] = Ah[cur][tg + 4][mb + g    ];
            ah[i][3] = Ah[cur][tg + 4][mb + g + 8];
            al[i][0] = Al[cur][tg    ][mb + g    ];
            al[i][1] = Al[cur][tg    ][mb + g + 8];
            al[i][2] = Al[cur][tg + 4][mb + g    ];
            al[i][3] = Al[cur][tg + 4][mb + g + 8];
        }
#pragma unroll
        for (int j = 0; j < NF; j++) {
            int nb = wn + j * 8;
            uint32_t b0h = Bh[cur][tg    ][nb + g];
            uint32_t b1h = Bh[cur][tg + 4][nb + g];
            uint32_t b0l = Bl[cur][tg    ][nb + g];
            uint32_t b1l = Bl[cur][tg + 4][nb + g];
#pragma unroll
            for (int i = 0; i < 4; i++) {
                mma_bf16(acc[i][j], ah[i][0], ah[i][1], ah[i][2], ah[i][3], b0h, b1h);
                mma_bf16(acc[i][j], ah[i][0], ah[i][1], ah[i][2], ah[i][3], b0l, b1l);
                mma_bf16(acc[i][j], al[i][0], al[i][1], al[i][2], al[i][3], b0h, b1h);
            }
        }

        if (kt + 1 < nk) sstore(cur ^ 1);
        __syncthreads();
        cur ^= 1;
    }
    cur ^= 1;   // stage that held the last tile (unused; epilogue below)

    auto emit = [&](int m, int n, float v) {
        if (m >= M || n >= N) return;
        if (EPI == EPI_STORE) {
            C[(size_t)m * ldc + n] = v;
        } else if (EPI == EPI_SOFTPLUS) {
            v += bias[n];
            C[(size_t)m * ldc + n] = (v > 20.f) ? v : log1pf(__expf(v));
        } else if (EPI == EPI_RESID) {
            int b = m / LL, l = m - b * LL;
            int lo = map_row(l, dir);
            int row = b * LL + lo;
            C[((size_t)row * 2 + dir) * CM + n] = aux[(size_t)row * CM + n] + v;
        } else if (EPI == EPI_GATE) {
            float gg = sigmoidf_(v + bias[n]);
            float of = aux[(size_t)m * (2 * CM) + n];
            float ob = aux[(size_t)m * (2 * CM) + CM + n];
            C[(size_t)m * ldc + n] = gg * of + (1.f - gg) * ob;
        } else {
            C[(size_t)m * ldc + n] = v + bias[n];
        }
    };

#pragma unroll
    for (int i = 0; i < 4; i++) {
        int mr = m0 + wm + i * 16 + g;
#pragma unroll
        for (int j = 0; j < NF; j++) {
            int nc = n0 + wn + j * 8 + 2 * tg;
            emit(mr,     nc,     acc[i][j][0]);
            emit(mr,     nc + 1, acc[i][j][1]);
            emit(mr + 8, nc,     acc[i][j][2]);
            emit(mr + 8, nc + 1, acc[i][j][3]);
        }
    }
}

// ---------------------------------------------------------------------------
// SIMT split-K GEMM for the skinny x_proj (N=80)
// ---------------------------------------------------------------------------
template <int TM, int TN, int TK, int KS>
__global__ void __launch_bounds__(256, 2)
gemm_splitk(const float* __restrict__ Ab, int lda, size_t sA,
            const float* __restrict__ Wb, size_t sW,
            float* __restrict__ Cb, int ldc, size_t sC,
            int M, int N, int K) {
    constexpr int RM = TM / 16;
    constexpr int RN = TN / 16;
    constexpr int A4 = TM * TK / 4;
    constexpr int B4 = TN * TK / 4;
    constexpr int RA = (A4 + 255) / 256;
    constexpr int RB = (B4 + 255) / 256;

    __shared__ float As[2][TK][TM + 4];
    __shared__ float Bs[2][TK][TN + 4];

    const int t  = threadIdx.x;
    const int tx = t & 15;
    const int ty = t >> 4;
    const int m0 = blockIdx.y * TM;
    const int n0 = blockIdx.x * TN;

    const int z = blockIdx.z;
    const int dir   = z / KS;
    const int split = z % KS;

    const float* A = Ab + (size_t)dir * sA;
    const float* W = Wb + (size_t)dir * sW;
    float*       C = Cb + (size_t)dir * sC;

    const int Kpart = K / KS;
    const int kbeg  = split * Kpart;
    const int nk    = Kpart / TK;

    float4 ra[RA], rb[RB];

    auto gload = [&](int k0) {
#pragma unroll
        for (int i = 0; i < RA; i++) {
            int idx = t + i * 256;
            float4 v = make_float4(0.f, 0.f, 0.f, 0.f);
            if (idx < A4) {
                int m = idx / (TK / 4), kq = idx % (TK / 4);
                int gm = m0 + m;
                if (gm < M) v = *(const float4*)&A[(size_t)gm * lda + k0 + kq * 4];
            }
            ra[i] = v;
        }
#pragma unroll
        for (int i = 0; i < RB; i++) {
            int idx = t + i * 256;
            float4 v = make_float4(0.f, 0.f, 0.f, 0.f);
            if (idx < B4) {
                int n = idx / (TK / 4), kq = idx % (TK / 4);
                int gn = n0 + n;
                if (gn < N) v = *(const float4*)&W[(size_t)gn * K + k0 + kq * 4];
            }
            rb[i] = v;
        }
    };
    auto sstore = [&](int s) {
#pragma unroll
        for (int i = 0; i < RA; i++) {
            int idx = t + i * 256;
            if (idx < A4) {
                int m = idx / (TK / 4), kq = (idx % (TK / 4)) * 4;
                As[s][kq + 0][m] = ra[i].x; As[s][kq + 1][m] = ra[i].y;
                As[s][kq + 2][m] = ra[i].z; As[s][kq + 3][m] = ra[i].w;
            }
        }
#pragma unroll
        for (int i = 0; i < RB; i++) {
            int idx = t + i * 256;
            if (idx < B4) {
                int n = idx / (TK / 4), kq = (idx % (TK / 4)) * 4;
                Bs[s][kq + 0][n] = rb[i].x; Bs[s][kq + 1][n] = rb[i].y;
                Bs[s][kq + 2][n] = rb[i].z; Bs[s][kq + 3][n] = rb[i].w;
            }
        }
    };

    float acc[RM][RN];
#pragma unroll
    for (int i = 0; i < RM; i++)
#pragma unroll
        for (int j = 0; j < RN; j++) acc[i][j] = 0.f;

    gload(kbeg);
    sstore(0);
    __syncthreads();

    int cur = 0;
    for (int kt = 0; kt < nk; kt++) {
        if (kt + 1 < nk) gload(kbeg + (kt + 1) * TK);
#pragma unroll
        for (int k = 0; k < TK; k++) {
            float af[RM], bf[RN];
#pragma unroll
            for (int i = 0; i < RM; i++) af[i] = As[cur][k][ty * RM + i];
#pragma unroll
            for (int j = 0; j < RN; j++) bf[j] = Bs[cur][k][tx * RN + j];
#pragma unroll
            for (int i = 0; i < RM; i++)
#pragma unroll
                for (int j = 0; j < RN; j++)
                    acc[i][j] = fmaf(af[i], bf[j], acc[i][j]);
        }
        __syncthreads();
        if (kt + 1 < nk) {
            sstore(cur ^ 1);
            __syncthreads();
            cur ^= 1;
        }
    }

#pragma unroll
    for (int i = 0; i < RM; i++) {
        int m = m0 + ty * RM + i;
        if (m >= M) continue;
#pragma unroll
        for (int j = 0; j < RN; j++) {
            int n = n0 + tx * RN + j;
            if (n >= N) continue;
            atomicAdd(&C[(size_t)m * ldc + n], acc[i][j]);
        }
    }
}

// ---------------------------------------------------------------------------
__global__ void conv_silu_kernel(const float* __restrict__ conv_w,
                                 const float* __restrict__ conv_b) {
    int idx = blockIdx.x * blockDim.x + threadIdx.x;
    if (idx >= 2 * MM * DI) return;
    int d = idx % DI;
    int r = idx / DI;
    int dir = r / MM;
    int l = r % LL;

    const float* w = conv_w + (size_t)(dir * DI + d) * DCONV;
    float acc = conv_b[dir * DI + d];
#pragma unroll
    for (int j = 0; j < DCONV; j++) {
        int ls = l - (DCONV - 1) + j;
        if (ls >= 0)
            acc = fmaf(w[j], g_xz[(size_t)(r - (DCONV - 1) + j) * (2 * DI) + d], acc);
    }
    g_xb[(size_t)r * DI + d] = siluf_(acc);
}

// ---------------------------------------------------------------------------
__global__ void __launch_bounds__(128, 8)
scan_kernel(const float* __restrict__ Dp) {
    int d   = blockIdx.x * blockDim.x + threadIdx.x;
    int b   = blockIdx.y;
    int dir = blockIdx.z;
    if (d >= DI) return;

    const float* Arow = &g_A[(dir * DI + d) * DS];
    float a0 = Arow[0];
    float da = Arow[1] - Arow[0];
    float Ar[DS];
    bool arith = (g_arith != 0);
    if (!arith) {
#pragma unroll
        for (int n = 0; n < DS; n++) Ar[n] = Arow[n];
    }

    float h[DS];
#pragma unroll
    for (int n = 0; n < DS; n++) h[n] = 0.f;

    float Dd = Dp[dir * DI + d];
    size_t r0 = (size_t)dir * MM + (size_t)b * LL;

    for (int l = 0; l < LL; l++) {
        size_t r = r0 + l;
        float u  = g_xb[r * DI + d];
        float dt = g_dt[r * DI + d];
        const float4* BC = (const float4*)(&g_xdbl[r * 80 + DR]);
        float4 Bv0 = __ldg(&BC[0]), Bv1 = __ldg(&BC[1]);
        float4 Bv2 = __ldg(&BC[2]), Bv3 = __ldg(&BC[3]);
        float4 Cv0 = __ldg(&BC[4]), Cv1 = __ldg(&BC[5]);
        float4 Cv2 = __ldg(&BC[6]), Cv3 = __ldg(&BC[7]);
        float Bl[DS] = {Bv0.x, Bv0.y, Bv0.z, Bv0.w, Bv1.x, Bv1.y, Bv1.z, Bv1.w,
                        Bv2.x, Bv2.y, Bv2.z, Bv2.w, Bv3.x, Bv3.y, Bv3.z, Bv3.w};
        float Cl[DS] = {Cv0.x, Cv0.y, Cv0.z, Cv0.w, Cv1.x, Cv1.y, Cv1.z, Cv1.w,
                        Cv2.x, Cv2.y, Cv2.z, Cv2.w, Cv3.x, Cv3.y, Cv3.z, Cv3.w};

        float du = dt * u;
        float yv = 0.f;
        if (arith) {
            float p  = __expf(dt * a0);
            float rr = __expf(dt * da);
#pragma unroll
            for (int n = 0; n < DS; n++) {
                h[n] = fmaf(p, h[n], du * Bl[n]);
                yv   = fmaf(h[n], Cl[n], yv);
                p *= rr;
            }
        } else {
#pragma unroll
            for (int n = 0; n < DS; n++) {
                float p = __expf(dt * Ar[n]);
                h[n] = fmaf(p, h[n], du * Bl[n]);
                yv   = fmaf(h[n], Cl[n], yv);
            }
        }
        yv = fmaf(u, Dd, yv);
        float z = g_xz[r * (2 * DI) + DI + d];
        g_y[r * DI + d] = yv * siluf_(z);
    }
}

// ---------------------------------------------------------------------------
extern "C" void kernel_launch(void* const* d_in, const int* in_sizes, int n_in,
                              void* d_out, int out_size) {
    const float* x         = (const float*)d_in[0];
    const float* norm_w    = (const float*)d_in[1];
    const float* in_proj_w = (const float*)d_in[2];
    const float* conv_w    = (const float*)d_in[3];
    const float* conv_b    = (const float*)d_in[4];
    const float* x_proj_w  = (const float*)d_in[5];
    const float* dt_proj_w = (const float*)d_in[6];
    const float* dt_proj_b = (const float*)d_in[7];
    const float* A_log     = (const float*)d_in[8];
    const float* Dp        = (const float*)d_in[9];
    const float* mix_out_w = (const float*)d_in[10];
    const float* gate_w    = (const float*)d_in[11];
    const float* gate_b    = (const float*)d_in[12];
    const float* proj_w    = (const float*)d_in[13];
    const float* proj_b    = (const float*)d_in[14];
    float* out = (float*)d_out;

    float *xn, *xz, *xb, *xdbl, *dt, *y, *o_out, *comb;
    cudaGetSymbolAddress((void**)&xn,    g_xn);
    cudaGetSymbolAddress((void**)&xz,    g_xz);
    cudaGetSymbolAddress((void**)&xb,    g_xb);
    cudaGetSymbolAddress((void**)&xdbl,  g_xdbl);
    cudaGetSymbolAddress((void**)&dt,    g_dt);
    cudaGetSymbolAddress((void**)&y,     g_y);
    cudaGetSymbolAddress((void**)&o_out, g_out);
    cudaGetSymbolAddress((void**)&comb,  g_comb);

    setup_A_kernel<<<(2 * DI * DS + 255) / 256, 256>>>(A_log);
    check_arith_kernel<<<1, 256>>>();

    rmsnorm_kernel<<<2 * MM, 256>>>(x, norm_w);

    const int MY = (MM + 127) / 128;   // 13

    // in_proj: (1568x768) @ (3072x768)^T
    gemm_bf16x2<EPI_STORE><<<dim3(2 * DI / 64, MY, 2), 256>>>(
        xn, CM, (size_t)MM * CM,
        in_proj_w, (size_t)2 * DI * CM,
        xz, 2 * DI, (size_t)MM * 2 * DI,
        MM, 2 * DI, CM, nullptr, 0, nullptr);

    conv_silu_kernel<<<(2 * MM * DI + 255) / 256, 256>>>(conv_w, conv_b);

    // x_proj: (1568x1536) @ (80x1536)^T, split-K=8 SIMT
    cudaMemsetAsync(xdbl, 0, sizeof(float) * 2 * MM * 80);
    gemm_splitk<128, 80, 16, 8><<<dim3(1, MY, 2 * 8), 256>>>(
        xb, DI, (size_t)MM * DI,
        x_proj_w, (size_t)80 * DI,
        xdbl, 80, (size_t)MM * 80,
        MM, 80, DI);

    // dt_proj + softplus: (1568x48) @ (1536x48)^T
    gemm_bf16x2<EPI_SOFTPLUS><<<dim3(DI / 64, MY, 2), 256>>>(
        xdbl, 80, (size_t)MM * 80,
        dt_proj_w, (size_t)DI * DR,
        dt, DI, (size_t)MM * DI,
        MM, DI, DR, dt_proj_b, DI, nullptr);

    scan_kernel<<<dim3(DI / 128, BB, 2), 128>>>(Dp);

    // out_proj + residual + flip-scatter
    gemm_bf16x2<EPI_RESID><<<dim3(CM / 64, MY, 2), 256>>>(
        y, DI, (size_t)MM * DI,
        mix_out_w, (size_t)CM * DI,
        o_out, 0, 0,
        MM, CM, DI, nullptr, 0, x);

    // gate GEMM + sigmoid combine
    gemm_bf16x2<EPI_GATE><<<dim3(CM / 64, MY, 1), 256>>>(
        o_out, 2 * CM, 0,
        gate_w, 0,
        comb, CM, 0,
        MM, CM, 2 * CM, gate_b, 0, o_out);

    // final projection + bias
    gemm_bf16x2<EPI_BIAS><<<dim3(CM / 64, MY, 1), 256>>>(
        comb, CM, 0,
        proj_w, 0,
        out, CM, 0,
        MM, CM, CM, proj_b, 0, nullptr);

    (void)in_sizes; (void)n_in; (void)out_size;
}

// round 6
// speedup vs baseline: 1.4696x; 1.0919x over previous
#include <cuda_runtime.h>
#include <cuda_bf16.h>
#include <cstdint>

// ---------------------------------------------------------------------------
// BiMamba refiner block, round 5: bf16x2 error-split MMA GEMMs with
// ldmatrix fragment loads + STS.128 swizzled staging (kill the LDS bottleneck).
// ---------------------------------------------------------------------------

#define BB      2
#define TT      4
#define NP      196
#define LL      784
#define MM      1568
#define CM      768
#define DI      1536
#define DS      16
#define DR      48
#define DCONV   4

// ---------------- scratch ---------------------------------------------------
__device__ float g_xn  [2 * MM * CM];
__device__ float g_xz  [2 * MM * 2 * DI];
__device__ float g_xb  [2 * MM * DI];
__device__ float g_xdbl[2 * MM * 80];
__device__ float g_dt  [2 * MM * DI];
__device__ float g_y   [2 * MM * DI];
__device__ float g_out [MM * 2 * CM];
__device__ float g_comb[MM * CM];
__device__ float g_A   [2 * DI * DS];
__device__ int   g_arith;

__device__ __forceinline__ int map_row(int l, int dir) {
    if (dir == 0) return l;
    int t = l / NP, n = l - t * NP;
    return (TT - 1 - t) * NP + n;
}
__device__ __forceinline__ float sigmoidf_(float v) { return 1.0f / (1.0f + __expf(-v)); }
__device__ __forceinline__ float siluf_(float v)    { return v * sigmoidf_(v); }

// pack two floats into bf16x2 hi and lo residual
__device__ __forceinline__ void split2(float x, float y, uint32_t& hi, uint32_t& lo) {
    __nv_bfloat16 hx = __float2bfloat16(x);
    __nv_bfloat16 hy = __float2bfloat16(y);
    __nv_bfloat16 lx = __float2bfloat16(x - __bfloat162float(hx));
    __nv_bfloat16 ly = __float2bfloat16(y - __bfloat162float(hy));
    __nv_bfloat162 h2 = __halves2bfloat162(hx, hy);
    __nv_bfloat162 l2 = __halves2bfloat162(lx, ly);
    hi = *reinterpret_cast<uint32_t*>(&h2);
    lo = *reinterpret_cast<uint32_t*>(&l2);
}

__device__ __forceinline__ void mma_bf16(float c[4],
                                         uint32_t a0, uint32_t a1, uint32_t a2, uint32_t a3,
                                         uint32_t b0, uint32_t b1) {
    asm volatile(
        "mma.sync.aligned.m16n8k16.row.col.f32.bf16.bf16.f32 "
        "{%0,%1,%2,%3},{%4,%5,%6,%7},{%8,%9},{%0,%1,%2,%3};"
        : "+f"(c[0]), "+f"(c[1]), "+f"(c[2]), "+f"(c[3])
        : "r"(a0), "r"(a1), "r"(a2), "r"(a3), "r"(b0), "r"(b1));
}

__device__ __forceinline__ void ldsm_x4(uint32_t& r0, uint32_t& r1, uint32_t& r2,
                                        uint32_t& r3, uint32_t addr) {
    asm volatile("ldmatrix.sync.aligned.m8n8.x4.shared.b16 {%0,%1,%2,%3}, [%4];"
                 : "=r"(r0), "=r"(r1), "=r"(r2), "=r"(r3) : "r"(addr));
}

// swizzled 16B-chunk index for (row, chunk) in a [rows][2-chunk] tile
__device__ __forceinline__ int swz(int row, int chunk) {
    return row * 2 + (chunk ^ ((row >> 2) & 1));
}

// ---------------------------------------------------------------------------
__global__ void setup_A_kernel(const float* __restrict__ A_log) {
    int i = blockIdx.x * blockDim.x + threadIdx.x;
    if (i < 2 * DI * DS) g_A[i] = -expf(A_log[i]);
}

__global__ void check_arith_kernel() {
    __shared__ int bad;
    if (threadIdx.x == 0) bad = 0;
    __syncthreads();
    for (int row = threadIdx.x; row < 2 * DI; row += blockDim.x) {
        const float* a = &g_A[row * DS];
        float a0 = a[0], da = a[1] - a[0];
        for (int n = 2; n < DS; n++) {
            float expect = a0 + n * da;
            if (fabsf(a[n] - expect) > 1e-4f * (1.0f + fabsf(a[n]))) { bad = 1; break; }
        }
    }
    __syncthreads();
    if (threadIdx.x == 0) g_arith = bad ? 0 : 1;
}

__global__ void rmsnorm_kernel(const float* __restrict__ x,
                               const float* __restrict__ norm_w) {
    int gid = blockIdx.x;
    int dir = gid / MM;
    int rem = gid - dir * MM;
    int b   = rem / LL, l = rem - b * LL;
    int lo  = map_row(l, dir);
    const float* row = x + (size_t)(b * LL + lo) * CM;

    float s = 0.f;
    for (int c = threadIdx.x; c < CM; c += blockDim.x) {
        float v = row[c];
        s += v * v;
    }
    __shared__ float warp_s[8];
    for (int off = 16; off > 0; off >>= 1) s += __shfl_down_sync(0xffffffffu, s, off);
    if ((threadIdx.x & 31) == 0) warp_s[threadIdx.x >> 5] = s;
    __syncthreads();
    if (threadIdx.x < 8) {
        float t = warp_s[threadIdx.x];
        for (int off = 4; off > 0; off >>= 1) t += __shfl_down_sync(0xffu, t, off);
        if (threadIdx.x == 0) warp_s[0] = t;
    }
    __syncthreads();
    float scale = rsqrtf(warp_s[0] / (float)CM + 1e-5f);

    float* dst = g_xn + (size_t)gid * CM;
    const float* nw = norm_w + dir * CM;
    for (int c = threadIdx.x; c < CM; c += blockDim.x)
        dst[c] = row[c] * scale * nw[c];
}

// ---------------------------------------------------------------------------
// bf16x2 tensor-core GEMM with ldmatrix: C[M,N] = A[M,K] * W[N,K]^T
// BM=128, BN=64, BK=16. 8 warps (2m x 4n), warp tile 64x16.
// smem: [row][16 bf16] rows (2x16B chunks, XOR-swizzled).
// ---------------------------------------------------------------------------
#define EPI_STORE    0
#define EPI_SOFTPLUS 1
#define EPI_RESID    2
#define EPI_GATE     3
#define EPI_BIAS     4

template <int EPI>
__global__ void __launch_bounds__(256, 2)
gemm_bf16x2(const float* __restrict__ Ab, int lda, size_t sA,
            const float* __restrict__ Wb, size_t sW,
            float* __restrict__ Cb, int ldc, size_t sC,
            int M, int N, int K,
            const float* __restrict__ biasb, size_t sBias,
            const float* __restrict__ aux) {
    constexpr int BM = 128, BN = 64;
    constexpr int NF = 2;

    // [stage][row*2 chunks] of 16B
    __shared__ uint4 AhS[2][BM * 2], AlS[2][BM * 2];
    __shared__ uint4 BhS[2][BN * 2], BlS[2][BN * 2];

    const int t    = threadIdx.x;
    const int lane = t & 31;
    const int w    = t >> 5;
    const int wm   = (w & 1) * 64;
    const int wn   = (w >> 1) * 16;
    const int g    = lane >> 2;
    const int tg   = lane & 3;

    const int m0  = blockIdx.y * BM;
    const int n0  = blockIdx.x * BN;
    const int dir = blockIdx.z;

    const float* A = Ab + (size_t)dir * sA;
    const float* W = Wb + (size_t)dir * sW;
    float*       C = Cb + (size_t)dir * sC;
    const float* bias = biasb ? biasb + (size_t)dir * sBias : nullptr;

    // staging assignment: A: thread t -> (row t>>1, chunk t&1)
    //                     B: threads 0..127 -> (row t>>1, chunk t&1)
    const int arow = t >> 1;
    const int akh  = (t & 1) * 8;      // k-offset of this thread's chunk
    const bool doB = (t < 128);
    const int brow = t >> 1;           // valid when doB

    float4 ra0, ra1, rb0, rb1;
    auto gload = [&](int k0) {
        int gm = m0 + arow;
        if (gm < M) {
            ra0 = *(const float4*)&A[(size_t)gm * lda + k0 + akh];
            ra1 = *(const float4*)&A[(size_t)gm * lda + k0 + akh + 4];
        } else {
            ra0 = make_float4(0.f, 0.f, 0.f, 0.f); ra1 = ra0;
        }
        if (doB) {
            int gn = n0 + brow;
            if (gn < N) {
                rb0 = *(const float4*)&W[(size_t)gn * K + k0 + akh];
                rb1 = *(const float4*)&W[(size_t)gn * K + k0 + akh + 4];
            } else {
                rb0 = make_float4(0.f, 0.f, 0.f, 0.f); rb1 = rb0;
            }
        }
    };
    auto sstore = [&](int s) {
        uint4 h4, l4;
        split2(ra0.x, ra0.y, h4.x, l4.x);
        split2(ra0.z, ra0.w, h4.y, l4.y);
        split2(ra1.x, ra1.y, h4.z, l4.z);
        split2(ra1.z, ra1.w, h4.w, l4.w);
        int ai = swz(arow, t & 1);
        AhS[s][ai] = h4; AlS[s][ai] = l4;
        if (doB) {
            split2(rb0.x, rb0.y, h4.x, l4.x);
            split2(rb0.z, rb0.w, h4.y, l4.y);
            split2(rb1.x, rb1.y, h4.z, l4.z);
            split2(rb1.z, rb1.w, h4.w, l4.w);
            int bi = swz(brow, t & 1);
            BhS[s][bi] = h4; BlS[s][bi] = l4;
        }
    };

    // ldmatrix lane->(row,chunk) maps
    const int a_r = lane & 15;          // + mb
    const int a_c = lane >> 4;          // 0/1
    const int b_r = wn + (lane & 7) + ((lane & 16) ? 8 : 0);
    const int b_c = (lane >> 3) & 1;

    const uint32_t baseAh = (uint32_t)__cvta_generic_to_shared(&AhS[0][0]);
    const uint32_t baseAl = (uint32_t)__cvta_generic_to_shared(&AlS[0][0]);
    const uint32_t baseBh = (uint32_t)__cvta_generic_to_shared(&BhS[0][0]);
    const uint32_t baseBl = (uint32_t)__cvta_generic_to_shared(&BlS[0][0]);
    const uint32_t strideA = BM * 2 * 16;   // bytes per stage
    const uint32_t strideB = BN * 2 * 16;

    float acc[4][NF][4];
#pragma unroll
    for (int i = 0; i < 4; i++)
#pragma unroll
        for (int j = 0; j < NF; j++)
#pragma unroll
            for (int r = 0; r < 4; r++) acc[i][j][r] = 0.f;

    const int nk = K / 16;
    gload(0);
    sstore(0);
    __syncthreads();

    int cur = 0;
    for (int kt = 0; kt < nk; kt++) {
        if (kt + 1 < nk) gload((kt + 1) * 16);

        uint32_t ah[4][4], al[4][4];
        uint32_t bh[4], bl[4];
        {
            uint32_t offB = (uint32_t)(swz(b_r, b_c) * 16);
            ldsm_x4(bh[0], bh[1], bh[2], bh[3], baseBh + cur * strideB + offB);
            ldsm_x4(bl[0], bl[1], bl[2], bl[3], baseBl + cur * strideB + offB);
        }
#pragma unroll
        for (int i = 0; i < 4; i++) {
            int row = wm + i * 16 + a_r;
            uint32_t off = (uint32_t)(swz(row, a_c) * 16);
            ldsm_x4(ah[i][0], ah[i][1], ah[i][2], ah[i][3], baseAh + cur * strideA + off);
            ldsm_x4(al[i][0], al[i][1], al[i][2], al[i][3], baseAl + cur * strideA + off);
        }

#pragma unroll
        for (int j = 0; j < NF; j++) {
            uint32_t b0h = bh[j * 2], b1h = bh[j * 2 + 1];
            uint32_t b0l = bl[j * 2], b1l = bl[j * 2 + 1];
#pragma unroll
            for (int i = 0; i < 4; i++) {
                mma_bf16(acc[i][j], ah[i][0], ah[i][1], ah[i][2], ah[i][3], b0h, b1h);
                mma_bf16(acc[i][j], ah[i][0], ah[i][1], ah[i][2], ah[i][3], b0l, b1l);
                mma_bf16(acc[i][j], al[i][0], al[i][1], al[i][2], al[i][3], b0h, b1h);
            }
        }

        if (kt + 1 < nk) sstore(cur ^ 1);
        __syncthreads();
        cur ^= 1;
    }

    auto emit = [&](int m, int n, float v) {
        if (m >= M || n >= N) return;
        if (EPI == EPI_STORE) {
            C[(size_t)m * ldc + n] = v;
        } else if (EPI == EPI_SOFTPLUS) {
            v += bias[n];
            C[(size_t)m * ldc + n] = (v > 20.f) ? v : log1pf(__expf(v));
        } else if (EPI == EPI_RESID) {
            int b = m / LL, l = m - b * LL;
            int lo = map_row(l, dir);
            int row = b * LL + lo;
            C[((size_t)row * 2 + dir) * CM + n] = aux[(size_t)row * CM + n] + v;
        } else if (EPI == EPI_GATE) {
            float gg = sigmoidf_(v + bias[n]);
            float of = aux[(size_t)m * (2 * CM) + n];
            float ob = aux[(size_t)m * (2 * CM) + CM + n];
            C[(size_t)m * ldc + n] = gg * of + (1.f - gg) * ob;
        } else {
            C[(size_t)m * ldc + n] = v + bias[n];
        }
    };

#pragma unroll
    for (int i = 0; i < 4; i++) {
        int mr = m0 + wm + i * 16 + g;
#pragma unroll
        for (int j = 0; j < NF; j++) {
            int nc = n0 + wn + j * 8 + 2 * tg;
            emit(mr,     nc,     acc[i][j][0]);
            emit(mr,     nc + 1, acc[i][j][1]);
            emit(mr + 8, nc,     acc[i][j][2]);
            emit(mr + 8, nc + 1, acc[i][j][3]);
        }
    }
}

// ---------------------------------------------------------------------------
// SIMT split-K GEMM for the skinny x_proj (N=80)
// ---------------------------------------------------------------------------
template <int TM, int TN, int TK, int KS>
__global__ void __launch_bounds__(256, 2)
gemm_splitk(const float* __restrict__ Ab, int lda, size_t sA,
            const float* __restrict__ Wb, size_t sW,
            float* __restrict__ Cb, int ldc, size_t sC,
            int M, int N, int K) {
    constexpr int RM = TM / 16;
    constexpr int RN = TN / 16;
    constexpr int A4 = TM * TK / 4;
    constexpr int B4 = TN * TK / 4;
    constexpr int RA = (A4 + 255) / 256;
    constexpr int RB = (B4 + 255) / 256;

    __shared__ float As[2][TK][TM + 4];
    __shared__ float Bs[2][TK][TN + 4];

    const int t  = threadIdx.x;
    const int tx = t & 15;
    const int ty = t >> 4;
    const int m0 = blockIdx.y * TM;
    const int n0 = blockIdx.x * TN;

    const int z = blockIdx.z;
    const int dir   = z / KS;
    const int split = z % KS;

    const float* A = Ab + (size_t)dir * sA;
    const float* W = Wb + (size_t)dir * sW;
    float*       C = Cb + (size_t)dir * sC;

    const int Kpart = K / KS;
    const int kbeg  = split * Kpart;
    const int nk    = Kpart / TK;

    float4 ra[RA], rb[RB];

    auto gload = [&](int k0) {
#pragma unroll
        for (int i = 0; i < RA; i++) {
            int idx = t + i * 256;
            float4 v = make_float4(0.f, 0.f, 0.f, 0.f);
            if (idx < A4) {
                int m = idx / (TK / 4), kq = idx % (TK / 4);
                int gm = m0 + m;
                if (gm < M) v = *(const float4*)&A[(size_t)gm * lda + k0 + kq * 4];
            }
            ra[i] = v;
        }
#pragma unroll
        for (int i = 0; i < RB; i++) {
            int idx = t + i * 256;
            float4 v = make_float4(0.f, 0.f, 0.f, 0.f);
            if (idx < B4) {
                int n = idx / (TK / 4), kq = idx % (TK / 4);
                int gn = n0 + n;
                if (gn < N) v = *(const float4*)&W[(size_t)gn * K + k0 + kq * 4];
            }
            rb[i] = v;
        }
    };
    auto sstore = [&](int s) {
#pragma unroll
        for (int i = 0; i < RA; i++) {
            int idx = t + i * 256;
            if (idx < A4) {
                int m = idx / (TK / 4), kq = (idx % (TK / 4)) * 4;
                As[s][kq + 0][m] = ra[i].x; As[s][kq + 1][m] = ra[i].y;
                As[s][kq + 2][m] = ra[i].z; As[s][kq + 3][m] = ra[i].w;
            }
        }
#pragma unroll
        for (int i = 0; i < RB; i++) {
            int idx = t + i * 256;
            if (idx < B4) {
                int n = idx / (TK / 4), kq = (idx % (TK / 4)) * 4;
                Bs[s][kq + 0][n] = rb[i].x; Bs[s][kq + 1][n] = rb[i].y;
                Bs[s][kq + 2][n] = rb[i].z; Bs[s][kq + 3][n] = rb[i].w;
            }
        }
    };

    float acc[RM][RN];
#pragma unroll
    for (int i = 0; i < RM; i++)
#pragma unroll
        for (int j = 0; j < RN; j++) acc[i][j] = 0.f;

    gload(kbeg);
    sstore(0);
    __syncthreads();

    int cur = 0;
    for (int kt = 0; kt < nk; kt++) {
        if (kt + 1 < nk) gload(kbeg + (kt + 1) * TK);
#pragma unroll
        for (int k = 0; k < TK; k++) {
            float af[RM], bf[RN];
#pragma unroll
            for (int i = 0; i < RM; i++) af[i] = As[cur][k][ty * RM + i];
#pragma unroll
            for (int j = 0; j < RN; j++) bf[j] = Bs[cur][k][tx * RN + j];
#pragma unroll
            for (int i = 0; i < RM; i++)
#pragma unroll
                for (int j = 0; j < RN; j++)
                    acc[i][j] = fmaf(af[i], bf[j], acc[i][j]);
        }
        __syncthreads();
        if (kt + 1 < nk) {
            sstore(cur ^ 1);
            __syncthreads();
            cur ^= 1;
        }
    }

#pragma unroll
    for (int i = 0; i < RM; i++) {
        int m = m0 + ty * RM + i;
        if (m >= M) continue;
#pragma unroll
        for (int j = 0; j < RN; j++) {
            int n = n0 + tx * RN + j;
            if (n >= N) continue;
            atomicAdd(&C[(size_t)m * ldc + n], acc[i][j]);
        }
    }
}

// ---------------------------------------------------------------------------
__global__ void conv_silu_kernel(const float* __restrict__ conv_w,
                                 const float* __restrict__ conv_b) {
    int idx = blockIdx.x * blockDim.x + threadIdx.x;
    if (idx >= 2 * MM * DI) return;
    int d = idx % DI;
    int r = idx / DI;
    int dir = r / MM;
    int l = r % LL;

    const float* w = conv_w + (size_t)(dir * DI + d) * DCONV;
    float acc = conv_b[dir * DI + d];
#pragma unroll
    for (int j = 0; j < DCONV; j++) {
        int ls = l - (DCONV - 1) + j;
        if (ls >= 0)
            acc = fmaf(w[j], g_xz[(size_t)(r - (DCONV - 1) + j) * (2 * DI) + d], acc);
    }
    g_xb[(size_t)r * DI + d] = siluf_(acc);
}

// ---------------------------------------------------------------------------
__global__ void __launch_bounds__(128, 8)
scan_kernel(const float* __restrict__ Dp) {
    int d   = blockIdx.x * blockDim.x + threadIdx.x;
    int b   = blockIdx.y;
    int dir = blockIdx.z;
    if (d >= DI) return;

    const float* Arow = &g_A[(dir * DI + d) * DS];
    float a0 = Arow[0];
    float da = Arow[1] - Arow[0];
    float Ar[DS];
    bool arith = (g_arith != 0);
    if (!arith) {
#pragma unroll
        for (int n = 0; n < DS; n++) Ar[n] = Arow[n];
    }

    float h[DS];
#pragma unroll
    for (int n = 0; n < DS; n++) h[n] = 0.f;

    float Dd = Dp[dir * DI + d];
    size_t r0 = (size_t)dir * MM + (size_t)b * LL;

    for (int l = 0; l < LL; l++) {
        size_t r = r0 + l;
        float u  = g_xb[r * DI + d];
        float dt = g_dt[r * DI + d];
        const float4* BC = (const float4*)(&g_xdbl[r * 80 + DR]);
        float4 Bv0 = __ldg(&BC[0]), Bv1 = __ldg(&BC[1]);
        float4 Bv2 = __ldg(&BC[2]), Bv3 = __ldg(&BC[3]);
        float4 Cv0 = __ldg(&BC[4]), Cv1 = __ldg(&BC[5]);
        float4 Cv2 = __ldg(&BC[6]), Cv3 = __ldg(&BC[7]);
        float Bl[DS] = {Bv0.x, Bv0.y, Bv0.z, Bv0.w, Bv1.x, Bv1.y, Bv1.z, Bv1.w,
                        Bv2.x, Bv2.y, Bv2.z, Bv2.w, Bv3.x, Bv3.y, Bv3.z, Bv3.w};
        float Cl[DS] = {Cv0.x, Cv0.y, Cv0.z, Cv0.w, Cv1.x, Cv1.y, Cv1.z, Cv1.w,
                        Cv2.x, Cv2.y, Cv2.z, Cv2.w, Cv3.x, Cv3.y, Cv3.z, Cv3.w};

        float du = dt * u;
        float yv = 0.f;
        if (arith) {
            float p  = __expf(dt * a0);
            float rr = __expf(dt * da);
#pragma unroll
            for (int n = 0; n < DS; n++) {
                h[n] = fmaf(p, h[n], du * Bl[n]);
                yv   = fmaf(h[n], Cl[n], yv);
                p *= rr;
            }
        } else {
#pragma unroll
            for (int n = 0; n < DS; n++) {
                float p = __expf(dt * Ar[n]);
                h[n] = fmaf(p, h[n], du * Bl[n]);
                yv   = fmaf(h[n], Cl[n], yv);
            }
        }
        yv = fmaf(u, Dd, yv);
        float z = g_xz[r * (2 * DI) + DI + d];
        g_y[r * DI + d] = yv * siluf_(z);
    }
}

// ---------------------------------------------------------------------------
extern "C" void kernel_launch(void* const* d_in, const int* in_sizes, int n_in,
                              void* d_out, int out_size) {
    const float* x         = (const float*)d_in[0];
    const float* norm_w    = (const float*)d_in[1];
    const float* in_proj_w = (const float*)d_in[2];
    const float* conv_w    = (const float*)d_in[3];
    const float* conv_b    = (const float*)d_in[4];
    const float* x_proj_w  = (const float*)d_in[5];
    const float* dt_proj_w = (const float*)d_in[6];
    const float* dt_proj_b = (const float*)d_in[7];
    const float* A_log     = (const float*)d_in[8];
    const float* Dp        = (const float*)d_in[9];
    const float* mix_out_w = (const float*)d_in[10];
    const float* gate_w    = (const float*)d_in[11];
    const float* gate_b    = (const float*)d_in[12];
    const float* proj_w    = (const float*)d_in[13];
    const float* proj_b    = (const float*)d_in[14];
    float* out = (float*)d_out;

    float *xn, *xz, *xb, *xdbl, *dt, *y, *o_out, *comb;
    cudaGetSymbolAddress((void**)&xn,    g_xn);
    cudaGetSymbolAddress((void**)&xz,    g_xz);
    cudaGetSymbolAddress((void**)&xb,    g_xb);
    cudaGetSymbolAddress((void**)&xdbl,  g_xdbl);
    cudaGetSymbolAddress((void**)&dt,    g_dt);
    cudaGetSymbolAddress((void**)&y,     g_y);
    cudaGetSymbolAddress((void**)&o_out, g_out);
    cudaGetSymbolAddress((void**)&comb,  g_comb);

    setup_A_kernel<<<(2 * DI * DS + 255) / 256, 256>>>(A_log);
    check_arith_kernel<<<1, 256>>>();

    rmsnorm_kernel<<<2 * MM, 256>>>(x, norm_w);

    const int MY = (MM + 127) / 128;   // 13

    // in_proj: (1568x768) @ (3072x768)^T
    gemm_bf16x2<EPI_STORE><<<dim3(2 * DI / 64, MY, 2), 256>>>(
        xn, CM, (size_t)MM * CM,
        in_proj_w, (size_t)2 * DI * CM,
        xz, 2 * DI, (size_t)MM * 2 * DI,
        MM, 2 * DI, CM, nullptr, 0, nullptr);

    conv_silu_kernel<<<(2 * MM * DI + 255) / 256, 256>>>(conv_w, conv_b);

    // x_proj: (1568x1536) @ (80x1536)^T, split-K=8 SIMT
    cudaMemsetAsync(xdbl, 0, sizeof(float) * 2 * MM * 80);
    gemm_splitk<128, 80, 16, 8><<<dim3(1, MY, 2 * 8), 256>>>(
        xb, DI, (size_t)MM * DI,
        x_proj_w, (size_t)80 * DI,
        xdbl, 80, (size_t)MM * 80,
        MM, 80, DI);

    // dt_proj + softplus: (1568x48) @ (1536x48)^T
    gemm_bf16x2<EPI_SOFTPLUS><<<dim3(DI / 64, MY, 2), 256>>>(
        xdbl, 80, (size_t)MM * 80,
        dt_proj_w, (size_t)DI * DR,
        dt, DI, (size_t)MM * DI,
        MM, DI, DR, dt_proj_b, DI, nullptr);

    scan_kernel<<<dim3(DI / 128, BB, 2), 128>>>(Dp);

    // out_proj + residual + flip-scatter
    gemm_bf16x2<EPI_RESID><<<dim3(CM / 64, MY, 2), 256>>>(
        y, DI, (size_t)MM * DI,
        mix_out_w, (size_t)CM * DI,
        o_out, 0, 0,
        MM, CM, DI, nullptr, 0, x);

    // gate GEMM + sigmoid combine
    gemm_bf16x2<EPI_GATE><<<dim3(CM / 64, MY, 1), 256>>>(
        o_out, 2 * CM, 0,
        gate_w, 0,
        comb, CM, 0,
        MM, CM, 2 * CM, gate_b, 0, o_out);

    // final projection + bias
    gemm_bf16x2<EPI_BIAS><<<dim3(CM / 64, MY, 1), 256>>>(
        comb, CM, 0,
        proj_w, 0,
        out, CM, 0,
        MM, CM, CM, proj_b, 0, nullptr);

    (void)in_sizes; (void)n_in; (void)out_size;
}

// round 8
// speedup vs baseline: 1.5222x; 1.0358x over previous
#include <cuda_runtime.h>
#include <cuda_bf16.h>
#include <cstdint>

// ---------------------------------------------------------------------------
// BiMamba refiner block, round 7: bf16x2 error-split MMA GEMMs, BN=128 wide
// warp tiles (64x32) to cut smem crossbar traffic per FLOP by ~1.7x.
// ---------------------------------------------------------------------------

#define BB      2
#define TT      4
#define NP      196
#define LL      784
#define MM      1568
#define CM      768
#define DI      1536
#define DS      16
#define DR      48
#define DCONV   4

// ---------------- scratch ---------------------------------------------------
__device__ float g_xn  [2 * MM * CM];
__device__ float g_xz  [2 * MM * 2 * DI];
__device__ float g_xb  [2 * MM * DI];
__device__ float g_xdbl[2 * MM * 80];
__device__ float g_dt  [2 * MM * DI];
__device__ float g_y   [2 * MM * DI];
__device__ float g_out [MM * 2 * CM];
__device__ float g_comb[MM * CM];
__device__ float g_A   [2 * DI * DS];
__device__ int   g_arith;

__device__ __forceinline__ int map_row(int l, int dir) {
    if (dir == 0) return l;
    int t = l / NP, n = l - t * NP;
    return (TT - 1 - t) * NP + n;
}
__device__ __forceinline__ float sigmoidf_(float v) { return 1.0f / (1.0f + __expf(-v)); }
__device__ __forceinline__ float siluf_(float v)    { return v * sigmoidf_(v); }

// pack two floats into bf16x2 hi and lo residual
__device__ __forceinline__ void split2(float x, float y, uint32_t& hi, uint32_t& lo) {
    __nv_bfloat16 hx = __float2bfloat16(x);
    __nv_bfloat16 hy = __float2bfloat16(y);
    __nv_bfloat16 lx = __float2bfloat16(x - __bfloat162float(hx));
    __nv_bfloat16 ly = __float2bfloat16(y - __bfloat162float(hy));
    __nv_bfloat162 h2 = __halves2bfloat162(hx, hy);
    __nv_bfloat162 l2 = __halves2bfloat162(lx, ly);
    hi = *reinterpret_cast<uint32_t*>(&h2);
    lo = *reinterpret_cast<uint32_t*>(&l2);
}

__device__ __forceinline__ void mma_bf16(float c[4],
                                         uint32_t a0, uint32_t a1, uint32_t a2, uint32_t a3,
                                         uint32_t b0, uint32_t b1) {
    asm volatile(
        "mma.sync.aligned.m16n8k16.row.col.f32.bf16.bf16.f32 "
        "{%0,%1,%2,%3},{%4,%5,%6,%7},{%8,%9},{%0,%1,%2,%3};"
        : "+f"(c[0]), "+f"(c[1]), "+f"(c[2]), "+f"(c[3])
        : "r"(a0), "r"(a1), "r"(a2), "r"(a3), "r"(b0), "r"(b1));
}

__device__ __forceinline__ void ldsm_x4(uint32_t& r0, uint32_t& r1, uint32_t& r2,
                                        uint32_t& r3, uint32_t addr) {
    asm volatile("ldmatrix.sync.aligned.m8n8.x4.shared.b16 {%0,%1,%2,%3}, [%4];"
                 : "=r"(r0), "=r"(r1), "=r"(r2), "=r"(r3) : "r"(addr));
}

// swizzled 16B-chunk index for (row, chunk) in a [rows][2-chunk] tile
__device__ __forceinline__ int swz(int row, int chunk) {
    return row * 2 + (chunk ^ ((row >> 2) & 1));
}

// ---------------------------------------------------------------------------
__global__ void setup_A_kernel(const float* __restrict__ A_log) {
    int i = blockIdx.x * blockDim.x + threadIdx.x;
    if (i < 2 * DI * DS) g_A[i] = -expf(A_log[i]);
}

__global__ void check_arith_kernel() {
    __shared__ int bad;
    if (threadIdx.x == 0) bad = 0;
    __syncthreads();
    for (int row = threadIdx.x; row < 2 * DI; row += blockDim.x) {
        const float* a = &g_A[row * DS];
        float a0 = a[0], da = a[1] - a[0];
        for (int n = 2; n < DS; n++) {
            float expect = a0 + n * da;
            if (fabsf(a[n] - expect) > 1e-4f * (1.0f + fabsf(a[n]))) { bad = 1; break; }
        }
    }
    __syncthreads();
    if (threadIdx.x == 0) g_arith = bad ? 0 : 1;
}

__global__ void rmsnorm_kernel(const float* __restrict__ x,
                               const float* __restrict__ norm_w) {
    int gid = blockIdx.x;
    int dir = gid / MM;
    int rem = gid - dir * MM;
    int b   = rem / LL, l = rem - b * LL;
    int lo  = map_row(l, dir);
    const float* row = x + (size_t)(b * LL + lo) * CM;

    float s = 0.f;
    for (int c = threadIdx.x; c < CM; c += blockDim.x) {
        float v = row[c];
        s += v * v;
    }
    __shared__ float warp_s[8];
    for (int off = 16; off > 0; off >>= 1) s += __shfl_down_sync(0xffffffffu, s, off);
    if ((threadIdx.x & 31) == 0) warp_s[threadIdx.x >> 5] = s;
    __syncthreads();
    if (threadIdx.x < 8) {
        float t = warp_s[threadIdx.x];
        for (int off = 4; off > 0; off >>= 1) t += __shfl_down_sync(0xffu, t, off);
        if (threadIdx.x == 0) warp_s[0] = t;
    }
    __syncthreads();
    float scale = rsqrtf(warp_s[0] / (float)CM + 1e-5f);

    float* dst = g_xn + (size_t)gid * CM;
    const float* nw = norm_w + dir * CM;
    for (int c = threadIdx.x; c < CM; c += blockDim.x)
        dst[c] = row[c] * scale * nw[c];
}

// ---------------------------------------------------------------------------
// bf16x2 tensor-core GEMM with ldmatrix: C[M,N] = A[M,K] * W[N,K]^T
// BM=128, BN=128, BK=16. 8 warps (2m x 4n), warp tile 64x32, NF=4.
// smem: [row][16 bf16] rows (2x16B chunks, XOR-swizzled).
// ---------------------------------------------------------------------------
#define EPI_STORE    0
#define EPI_SOFTPLUS 1
#define EPI_RESID    2
#define EPI_GATE     3
#define EPI_BIAS     4

template <int EPI>
__global__ void __launch_bounds__(256)
gemm_bf16x2(const float* __restrict__ Ab, int lda, size_t sA,
            const float* __restrict__ Wb, size_t sW,
            float* __restrict__ Cb, int ldc, size_t sC,
            int M, int N, int K,
            const float* __restrict__ biasb, size_t sBias,
            const float* __restrict__ aux) {
    constexpr int BM = 128, BN = 128;
    constexpr int NF = 4;

    __shared__ uint4 AhS[2][BM * 2], AlS[2][BM * 2];
    __shared__ uint4 BhS[2][BN * 2], BlS[2][BN * 2];

    const int t    = threadIdx.x;
    const int lane = t & 31;
    const int w    = t >> 5;
    const int wm   = (w & 1) * 64;
    const int wn   = (w >> 1) * 32;
    const int g    = lane >> 2;
    const int tg   = lane & 3;

    const int m0  = blockIdx.y * BM;
    const int n0  = blockIdx.x * BN;
    const int dir = blockIdx.z;

    const float* A = Ab + (size_t)dir * sA;
    const float* W = Wb + (size_t)dir * sW;
    float*       C = Cb + (size_t)dir * sC;
    const float* bias = biasb ? biasb + (size_t)dir * sBias : nullptr;

    // staging: every thread stages one (row, chunk) of A and of B
    const int srow = t >> 1;
    const int skh  = (t & 1) * 8;

    float4 ra0, ra1, rb0, rb1;
    auto gload = [&](int k0) {
        int gm = m0 + srow;
        if (gm < M) {
            ra0 = *(const float4*)&A[(size_t)gm * lda + k0 + skh];
            ra1 = *(const float4*)&A[(size_t)gm * lda + k0 + skh + 4];
        } else {
            ra0 = make_float4(0.f, 0.f, 0.f, 0.f); ra1 = ra0;
        }
        int gn = n0 + srow;
        if (gn < N) {
            rb0 = *(const float4*)&W[(size_t)gn * K + k0 + skh];
            rb1 = *(const float4*)&W[(size_t)gn * K + k0 + skh + 4];
        } else {
            rb0 = make_float4(0.f, 0.f, 0.f, 0.f); rb1 = rb0;
        }
    };
    auto sstore = [&](int s) {
        uint4 h4, l4;
        split2(ra0.x, ra0.y, h4.x, l4.x);
        split2(ra0.z, ra0.w, h4.y, l4.y);
        split2(ra1.x, ra1.y, h4.z, l4.z);
        split2(ra1.z, ra1.w, h4.w, l4.w);
        int ai = swz(srow, t & 1);
        AhS[s][ai] = h4; AlS[s][ai] = l4;
        split2(rb0.x, rb0.y, h4.x, l4.x);
        split2(rb0.z, rb0.w, h4.y, l4.y);
        split2(rb1.x, rb1.y, h4.z, l4.z);
        split2(rb1.z, rb1.w, h4.w, l4.w);
        BhS[s][ai] = h4; BlS[s][ai] = l4;
    };

    // ldmatrix lane->(row,chunk) maps
    const int a_r = lane & 15;          // + tile base
    const int a_c = lane >> 4;          // 0/1
    const int b_r = (lane & 7) + ((lane & 16) ? 8 : 0);
    const int b_c = (lane >> 3) & 1;

    const uint32_t baseAh = (uint32_t)__cvta_generic_to_shared(&AhS[0][0]);
    const uint32_t baseAl = (uint32_t)__cvta_generic_to_shared(&AlS[0][0]);
    const uint32_t baseBh = (uint32_t)__cvta_generic_to_shared(&BhS[0][0]);
    const uint32_t baseBl = (uint32_t)__cvta_generic_to_shared(&BlS[0][0]);
    const uint32_t strideA = BM * 2 * 16;
    const uint32_t strideB = BN * 2 * 16;

    float acc[4][NF][4];
#pragma unroll
    for (int i = 0; i < 4; i++)
#pragma unroll
        for (int j = 0; j < NF; j++)
#pragma unroll
            for (int r = 0; r < 4; r++) acc[i][j][r] = 0.f;

    const int nk = K / 16;
    gload(0);
    sstore(0);
    __syncthreads();

    int cur = 0;
    for (int kt = 0; kt < nk; kt++) {
        if (kt + 1 < nk) gload((kt + 1) * 16);

        uint32_t ah[4][4], al[4][4];
        uint32_t bh[8], bl[8];
        {
            uint32_t off0 = (uint32_t)(swz(wn + b_r,      b_c) * 16);
            uint32_t off1 = (uint32_t)(swz(wn + 16 + b_r, b_c) * 16);
            ldsm_x4(bh[0], bh[1], bh[2], bh[3], baseBh + cur * strideB + off0);
            ldsm_x4(bh[4], bh[5], bh[6], bh[7], baseBh + cur * strideB + off1);
            ldsm_x4(bl[0], bl[1], bl[2], bl[3], baseBl + cur * strideB + off0);
            ldsm_x4(bl[4], bl[5], bl[6], bl[7], baseBl + cur * strideB + off1);
        }
#pragma unroll
        for (int i = 0; i < 4; i++) {
            int row = wm + i * 16 + a_r;
            uint32_t off = (uint32_t)(swz(row, a_c) * 16);
            ldsm_x4(ah[i][0], ah[i][1], ah[i][2], ah[i][3], baseAh + cur * strideA + off);
            ldsm_x4(al[i][0], al[i][1], al[i][2], al[i][3], baseAl + cur * strideA + off);
        }

#pragma unroll
        for (int j = 0; j < NF; j++) {
            uint32_t b0h = bh[j * 2], b1h = bh[j * 2 + 1];
            uint32_t b0l = bl[j * 2], b1l = bl[j * 2 + 1];
#pragma unroll
            for (int i = 0; i < 4; i++) {
                mma_bf16(acc[i][j], ah[i][0], ah[i][1], ah[i][2], ah[i][3], b0h, b1h);
                mma_bf16(acc[i][j], ah[i][0], ah[i][1], ah[i][2], ah[i][3], b0l, b1l);
                mma_bf16(acc[i][j], al[i][0], al[i][1], al[i][2], al[i][3], b0h, b1h);
            }
        }

        if (kt + 1 < nk) sstore(cur ^ 1);
        __syncthreads();
        cur ^= 1;
    }

    auto emit = [&](int m, int n, float v) {
        if (m >= M || n >= N) return;
        if (EPI == EPI_STORE) {
            C[(size_t)m * ldc + n] = v;
        } else if (EPI == EPI_SOFTPLUS) {
            v += bias[n];
            C[(size_t)m * ldc + n] = (v > 20.f) ? v : log1pf(__expf(v));
        } else if (EPI == EPI_RESID) {
            int b = m / LL, l = m - b * LL;
            int lo = map_row(l, dir);
            int row = b * LL + lo;
            C[((size_t)row * 2 + dir) * CM + n] = aux[(size_t)row * CM + n] + v;
        } else if (EPI == EPI_GATE) {
            float gg = sigmoidf_(v + bias[n]);
            float of = aux[(size_t)m * (2 * CM) + n];
            float ob = aux[(size_t)m * (2 * CM) + CM + n];
            C[(size_t)m * ldc + n] = gg * of + (1.f - gg) * ob;
        } else {
            C[(size_t)m * ldc + n] = v + bias[n];
        }
    };

#pragma unroll
    for (int i = 0; i < 4; i++) {
        int mr = m0 + wm + i * 16 + g;
#pragma unroll
        for (int j = 0; j < NF; j++) {
            int nc = n0 + wn + j * 8 + 2 * tg;
            emit(mr,     nc,     acc[i][j][0]);
            emit(mr,     nc + 1, acc[i][j][1]);
            emit(mr + 8, nc,     acc[i][j][2]);
            emit(mr + 8, nc + 1, acc[i][j][3]);
        }
    }
}

// ---------------------------------------------------------------------------
// SIMT split-K GEMM for the skinny x_proj (N=80)
// ---------------------------------------------------------------------------
template <int TM, int TN, int TK, int KS>
__global__ void __launch_bounds__(256, 2)
gemm_splitk(const float* __restrict__ Ab, int lda, size_t sA,
            const float* __restrict__ Wb, size_t sW,
            float* __restrict__ Cb, int ldc, size_t sC,
            int M, int N, int K) {
    constexpr int RM = TM / 16;
    constexpr int RN = TN / 16;
    constexpr int A4 = TM * TK / 4;
    constexpr int B4 = TN * TK / 4;
    constexpr int RA = (A4 + 255) / 256;
    constexpr int RB = (B4 + 255) / 256;

    __shared__ float As[2][TK][TM + 4];
    __shared__ float Bs[2][TK][TN + 4];

    const int t  = threadIdx.x;
    const int tx = t & 15;
    const int ty = t >> 4;
    const int m0 = blockIdx.y * TM;
    const int n0 = blockIdx.x * TN;

    const int z = blockIdx.z;
    const int dir   = z / KS;
    const int split = z % KS;

    const float* A = Ab + (size_t)dir * sA;
    const float* W = Wb + (size_t)dir * sW;
    float*       C = Cb + (size_t)dir * sC;

    const int Kpart = K / KS;
    const int kbeg  = split * Kpart;
    const int nk    = Kpart / TK;

    float4 ra[RA], rb[RB];

    auto gload = [&](int k0) {
#pragma unroll
        for (int i = 0; i < RA; i++) {
            int idx = t + i * 256;
            float4 v = make_float4(0.f, 0.f, 0.f, 0.f);
            if (idx < A4) {
                int m = idx / (TK / 4), kq = idx % (TK / 4);
                int gm = m0 + m;
                if (gm < M) v = *(const float4*)&A[(size_t)gm * lda + k0 + kq * 4];
            }
            ra[i] = v;
        }
#pragma unroll
        for (int i = 0; i < RB; i++) {
            int idx = t + i * 256;
            float4 v = make_float4(0.f, 0.f, 0.f, 0.f);
            if (idx < B4) {
                int n = idx / (TK / 4), kq = idx % (TK / 4);
                int gn = n0 + n;
                if (gn < N) v = *(const float4*)&W[(size_t)gn * K + k0 + kq * 4];
            }
            rb[i] = v;
        }
    };
    auto sstore = [&](int s) {
#pragma unroll
        for (int i = 0; i < RA; i++) {
            int idx = t + i * 256;
            if (idx < A4) {
                int m = idx / (TK / 4), kq = (idx % (TK / 4)) * 4;
                As[s][kq + 0][m] = ra[i].x; As[s][kq + 1][m] = ra[i].y;
                As[s][kq + 2][m] = ra[i].z; As[s][kq + 3][m] = ra[i].w;
            }
        }
#pragma unroll
        for (int i = 0; i < RB; i++) {
            int idx = t + i * 256;
            if (idx < B4) {
                int n = idx / (TK / 4), kq = (idx % (TK / 4)) * 4;
                Bs[s][kq + 0][n] = rb[i].x; Bs[s][kq + 1][n] = rb[i].y;
                Bs[s][kq + 2][n] = rb[i].z; Bs[s][kq + 3][n] = rb[i].w;
            }
        }
    };

    float acc[RM][RN];
#pragma unroll
    for (int i = 0; i < RM; i++)
#pragma unroll
        for (int j = 0; j < RN; j++) acc[i][j] = 0.f;

    gload(kbeg);
    sstore(0);
    __syncthreads();

    int cur = 0;
    for (int kt = 0; kt < nk; kt++) {
        if (kt + 1 < nk) gload(kbeg + (kt + 1) * TK);
#pragma unroll
        for (int k = 0; k < TK; k++) {
            float af[RM], bf[RN];
#pragma unroll
            for (int i = 0; i < RM; i++) af[i] = As[cur][k][ty * RM + i];
#pragma unroll
            for (int j = 0; j < RN; j++) bf[j] = Bs[cur][k][tx * RN + j];
#pragma unroll
            for (int i = 0; i < RM; i++)
#pragma unroll
                for (int j = 0; j < RN; j++)
                    acc[i][j] = fmaf(af[i], bf[j], acc[i][j]);
        }
        __syncthreads();
        if (kt + 1 < nk) {
            sstore(cur ^ 1);
            __syncthreads();
            cur ^= 1;
        }
    }

#pragma unroll
    for (int i = 0; i < RM; i++) {
        int m = m0 + ty * RM + i;
        if (m >= M) continue;
#pragma unroll
        for (int j = 0; j < RN; j++) {
            int n = n0 + tx * RN + j;
            if (n >= N) continue;
            atomicAdd(&C[(size_t)m * ldc + n], acc[i][j]);
        }
    }
}

// ---------------------------------------------------------------------------
__global__ void conv_silu_kernel(const float* __restrict__ conv_w,
                                 const float* __restrict__ conv_b) {
    int idx = blockIdx.x * blockDim.x + threadIdx.x;
    if (idx >= 2 * MM * DI) return;
    int d = idx % DI;
    int r = idx / DI;
    int dir = r / MM;
    int l = r % LL;

    const float* w = conv_w + (size_t)(dir * DI + d) * DCONV;
    float acc = conv_b[dir * DI + d];
#pragma unroll
    for (int j = 0; j < DCONV; j++) {
        int ls = l - (DCONV - 1) + j;
        if (ls >= 0)
            acc = fmaf(w[j], g_xz[(size_t)(r - (DCONV - 1) + j) * (2 * DI) + d], acc);
    }
    g_xb[(size_t)r * DI + d] = siluf_(acc);
}

// ---------------------------------------------------------------------------
__global__ void __launch_bounds__(128, 8)
scan_kernel(const float* __restrict__ Dp) {
    int d   = blockIdx.x * blockDim.x + threadIdx.x;
    int b   = blockIdx.y;
    int dir = blockIdx.z;
    if (d >= DI) return;

    const float* Arow = &g_A[(dir * DI + d) * DS];
    float a0 = Arow[0];
    float da = Arow[1] - Arow[0];
    float Ar[DS];
    bool arith = (g_arith != 0);
    if (!arith) {
#pragma unroll
        for (int n = 0; n < DS; n++) Ar[n] = Arow[n];
    }

    float h[DS];
#pragma unroll
    for (int n = 0; n < DS; n++) h[n] = 0.f;

    float Dd = Dp[dir * DI + d];
    size_t r0 = (size_t)dir * MM + (size_t)b * LL;

    for (int l = 0; l < LL; l++) {
        size_t r = r0 + l;
        float u  = g_xb[r * DI + d];
        float dt = g_dt[r * DI + d];
        const float4* BC = (const float4*)(&g_xdbl[r * 80 + DR]);
        float4 Bv0 = __ldg(&BC[0]), Bv1 = __ldg(&BC[1]);
        float4 Bv2 = __ldg(&BC[2]), Bv3 = __ldg(&BC[3]);
        float4 Cv0 = __ldg(&BC[4]), Cv1 = __ldg(&BC[5]);
        float4 Cv2 = __ldg(&BC[6]), Cv3 = __ldg(&BC[7]);
        float Bl[DS] = {Bv0.x, Bv0.y, Bv0.z, Bv0.w, Bv1.x, Bv1.y, Bv1.z, Bv1.w,
                        Bv2.x, Bv2.y, Bv2.z, Bv2.w, Bv3.x, Bv3.y, Bv3.z, Bv3.w};
        float Cl[DS] = {Cv0.x, Cv0.y, Cv0.z, Cv0.w, Cv1.x, Cv1.y, Cv1.z, Cv1.w,
                        Cv2.x, Cv2.y, Cv2.z, Cv2.w, Cv3.x, Cv3.y, Cv3.z, Cv3.w};

        float du = dt * u;
        float yv = 0.f;
        if (arith) {
            float p  = __expf(dt * a0);
            float rr = __expf(dt * da);
#pragma unroll
            for (int n = 0; n < DS; n++) {
                h[n] = fmaf(p, h[n], du * Bl[n]);
                yv   = fmaf(h[n], Cl[n], yv);
                p *= rr;
            }
        } else {
#pragma unroll
            for (int n = 0; n < DS; n++) {
                float p = __expf(dt * Ar[n]);
                h[n] = fmaf(p, h[n], du * Bl[n]);
                yv   = fmaf(h[n], Cl[n], yv);
            }
        }
        yv = fmaf(u, Dd, yv);
        float z = g_xz[r * (2 * DI) + DI + d];
        g_y[r * DI + d] = yv * siluf_(z);
    }
}

// ---------------------------------------------------------------------------
extern "C" void kernel_launch(void* const* d_in, const int* in_sizes, int n_in,
                              void* d_out, int out_size) {
    const float* x         = (const float*)d_in[0];
    const float* norm_w    = (const float*)d_in[1];
    const float* in_proj_w = (const float*)d_in[2];
    const float* conv_w    = (const float*)d_in[3];
    const float* conv_b    = (const float*)d_in[4];
    const float* x_proj_w  = (const float*)d_in[5];
    const float* dt_proj_w = (const float*)d_in[6];
    const float* dt_proj_b = (const float*)d_in[7];
    const float* A_log     = (const float*)d_in[8];
    const float* Dp        = (const float*)d_in[9];
    const float* mix_out_w = (const float*)d_in[10];
    const float* gate_w    = (const float*)d_in[11];
    const float* gate_b    = (const float*)d_in[12];
    const float* proj_w    = (const float*)d_in[13];
    const float* proj_b    = (const float*)d_in[14];
    float* out = (float*)d_out;

    float *xn, *xz, *xb, *xdbl, *dt, *y, *o_out, *comb;
    cudaGetSymbolAddress((void**)&xn,    g_xn);
    cudaGetSymbolAddress((void**)&xz,    g_xz);
    cudaGetSymbolAddress((void**)&xb,    g_xb);
    cudaGetSymbolAddress((void**)&xdbl,  g_xdbl);
    cudaGetSymbolAddress((void**)&dt,    g_dt);
    cudaGetSymbolAddress((void**)&y,     g_y);
    cudaGetSymbolAddress((void**)&o_out, g_out);
    cudaGetSymbolAddress((void**)&comb,  g_comb);

    setup_A_kernel<<<(2 * DI * DS + 255) / 256, 256>>>(A_log);
    check_arith_kernel<<<1, 256>>>();

    rmsnorm_kernel<<<2 * MM, 256>>>(x, norm_w);

    const int MY = (MM + 127) / 128;   // 13

    // in_proj: (1568x768) @ (3072x768)^T
    gemm_bf16x2<EPI_STORE><<<dim3(2 * DI / 128, MY, 2), 256>>>(
        xn, CM, (size_t)MM * CM,
        in_proj_w, (size_t)2 * DI * CM,
        xz, 2 * DI, (size_t)MM * 2 * DI,
        MM, 2 * DI, CM, nullptr, 0, nullptr);

    conv_silu_kernel<<<(2 * MM * DI + 255) / 256, 256>>>(conv_w, conv_b);

    // x_proj: (1568x1536) @ (80x1536)^T, split-K=8 SIMT
    cudaMemsetAsync(xdbl, 0, sizeof(float) * 2 * MM * 80);
    gemm_splitk<128, 80, 16, 8><<<dim3(1, MY, 2 * 8), 256>>>(
        xb, DI, (size_t)MM * DI,
        x_proj_w, (size_t)80 * DI,
        xdbl, 80, (size_t)MM * 80,
        MM, 80, DI);

    // dt_proj + softplus: (1568x48) @ (1536x48)^T
    gemm_bf16x2<EPI_SOFTPLUS><<<dim3(DI / 128, MY, 2), 256>>>(
        xdbl, 80, (size_t)MM * 80,
        dt_proj_w, (size_t)DI * DR,
        dt, DI, (size_t)MM * DI,
        MM, DI, DR, dt_proj_b, DI, nullptr);

    scan_kernel<<<dim3(DI / 128, BB, 2), 128>>>(Dp);

    // out_proj + residual + flip-scatter
    gemm_bf16x2<EPI_RESID><<<dim3(CM / 128, MY, 2), 256>>>(
        y, DI, (size_t)MM * DI,
        mix_out_w, (size_t)CM * DI,
        o_out, 0, 0,
        MM, CM, DI, nullptr, 0, x);

    // gate GEMM + sigmoid combine
    gemm_bf16x2<EPI_GATE><<<dim3(CM / 128, MY, 1), 256>>>(
        o_out, 2 * CM, 0,
        gate_w, 0,
        comb, CM, 0,
        MM, CM, 2 * CM, gate_b, 0, o_out);

    // final projection + bias
    gemm_bf16x2<EPI_BIAS><<<dim3(CM / 128, MY, 1), 256>>>(
        comb, CM, 0,
        proj_w, 0,
        out, CM, 0,
        MM, CM, CM, proj_b, 0, nullptr);

    (void)in_sizes; (void)n_in; (void)out_size;
}